// round 4
// baseline (speedup 1.0000x reference)
#include <cuda_runtime.h>
#include <cuda_bf16.h>
#include <math.h>

#define B_   32
#define T_   50
#define TS_  49
#define D_   100
#define NEGF (-1000000000.0f)
#define NROW (B_*TS_)   // 1568

// ---------------- device scratch (no cudaMalloc allowed) ----------------
__device__ float g_e1[NROW*D_];
__device__ float g_e2[NROW*D_];
__device__ float g_et[NROW*D_];
__device__ float g_preg[NROW*400];
__device__ float g_u[NROW*D_];
__device__ float g_zq[NROW];
__device__ int   g_topk[NROW*10];
__device__ float g_vq[D_];
__device__ float g_vk[D_];

// =====================================================================
// k_prep: vq = W_query^T wA, vk = W_key^T wB  (bias terms cancel in softmax)
// =====================================================================
__global__ void k_prep(const float* __restrict__ Wq, const float* __restrict__ Wk,
                       const float* __restrict__ Ww)
{
    int d = threadIdx.x;
    if (d < D_) {
        float a = 0.f, c = 0.f;
        for (int e = 0; e < D_; e++) {
            a += Ww[e]       * Wq[e*D_ + d];
            c += Ww[D_ + e]  * Wk[e*D_ + d];
        }
        g_vq[d] = a; g_vk[d] = c;
    }
}

// =====================================================================
// k_agg helpers
// =====================================================================
// Stage W (row-major [100x100], W[o*100+k]) transposed into smem Wt[k*101+o].
// Global read coalesced; smem write stride 101 (gcd(5,32)=1) conflict-free.
__device__ __forceinline__ void stage_w(const float* __restrict__ Wg, float* __restrict__ Wt, int tid)
{
    for (int i = tid; i < 10000; i += 256)
        Wt[(i % 100) * 101 + (i / 100)] = Wg[i];
}

// out[r][o] = tanh( sum_k X[r][k]*Wt[k][o] + bias[o] ), RT rows x 4 cols per task.
// Columns strided by 25 so each of the 4 Wt loads is lane-consecutive (no conflicts).
template<int RT>
__device__ __forceinline__ void mm_tanh(const float* __restrict__ X, int rows,
                                        const float* __restrict__ Wt,
                                        const float* __restrict__ bias,
                                        float* __restrict__ out, int tid)
{
    int nrq = rows / RT;
    int tasks = nrq * 25;
    for (int task = tid; task < tasks; task += 256) {
        int rq = task / 25;
        int cq = task % 25;            // columns cq, cq+25, cq+50, cq+75
        const float* Xb = X + rq * RT * D_;
        float acc[RT][4];
        #pragma unroll
        for (int r = 0; r < RT; r++)
            #pragma unroll
            for (int c = 0; c < 4; c++) acc[r][c] = 0.f;
        #pragma unroll 4
        for (int k = 0; k < D_; k++) {
            const float* wr = Wt + k * 101 + cq;
            float w0 = wr[0], w1 = wr[25], w2 = wr[50], w3 = wr[75];
            #pragma unroll
            for (int r = 0; r < RT; r++) {
                float x = Xb[r * D_ + k];
                acc[r][0] += x * w0; acc[r][1] += x * w1;
                acc[r][2] += x * w2; acc[r][3] += x * w3;
            }
        }
        #pragma unroll
        for (int r = 0; r < RT; r++) {
            float* o = out + (rq * RT + r) * D_ + cq;
            o[0]  = tanhf(acc[r][0] + bias[cq]);
            o[25] = tanhf(acc[r][1] + bias[cq + 25]);
            o[50] = tanhf(acc[r][2] + bias[cq + 50]);
            o[75] = tanhf(acc[r][3] + bias[cq + 75]);
        }
    }
}

// smem layout (float offsets; all multiples of 4 for float4 use)
#define SM_WT   0
#define SM_E2   10100
#define SM_E2B  13700
#define SM_M3   17300
#define SM_E1   20900
#define SM_E1B  21500
#define SM_M2   22100
#define SM_E0   22700
#define SM_E0B  22800
#define SM_S    22900
#define SM_IDS  23000
#define AGG_SM_FLOATS 23264
#define AGG_SM_BYTES  (AGG_SM_FLOATS*4)

// =====================================================================
// k_agg: one block per (t, b, side). Full 3-hop aggregation in smem.
// =====================================================================
__global__ __launch_bounds__(256, 2)
void k_agg(const int* __restrict__ question, const int* __restrict__ user,
           const int* __restrict__ mask,
           const int* __restrict__ q_nb, const int* __restrict__ s_nb,
           const int* __restrict__ u_nb, const int* __restrict__ q_nb2,
           const float* __restrict__ emb_q, const float* __restrict__ emb_q2,
           const float* __restrict__ emb_s, const float* __restrict__ emb_u,
           const float* __restrict__ agg_w, const float* __restrict__ agg_b,
           const float* __restrict__ W_al,  const float* __restrict__ b_al)
{
    extern __shared__ float sm[];
    int t = blockIdx.x, b = blockIdx.y, side = blockIdx.z;
    int tid = threadIdx.x;
    int m  = mask[b*T_ + t];
    int qt = question[b*T_ + t];
    float* outp = (side == 0 ? g_e1 : g_e2) + (b*TS_ + t) * D_;

    if (m == 0) {
        const float* src = (side == 0 ? emb_q : emb_q2) + (size_t)qt * D_;
        for (int d = tid; d < D_; d += 256) outp[d] = src[d];
        return;
    }

    int n0; const int *tabE, *tabO; const float *embE, *embO;
    if (side == 0) { n0 = qt;            tabE = q_nb; tabO = s_nb;  embE = emb_q; embO = emb_s;  }
    else           { n0 = user[b*T_+t];  tabE = u_nb; tabO = q_nb2; embE = emb_u; embO = emb_q2; }

    int* ids1 = (int*)(sm + SM_IDS);
    int* ids2 = ids1 + 6;
    int* ids3 = ids2 + 36;
    const float4* embE4 = (const float4*)embE;
    const float4* embO4 = (const float4*)embO;

    if (tid < 6) ids1[tid] = tabE[n0*6 + tid];
    __syncthreads();
    if (tid < 36) ids2[tid] = tabO[ids1[tid/6]*6 + tid%6];
    // E1 = embO[ids1]  (6 rows)
    for (int i = tid; i < 150; i += 256) {
        int r = i/25, dq = i%25;
        ((float4*)(sm + SM_E1))[r*25 + dq] = embO4[(size_t)ids1[r]*25 + dq];
    }
    if (tid < 25) ((float4*)(sm + SM_E0))[tid] = embE4[(size_t)n0*25 + tid];
    __syncthreads();
    if (tid < 216) ids3[tid] = tabE[ids2[tid/6]*6 + tid%6];
    // E2 = embE[ids2]  (36 rows)
    for (int i = tid; i < 900; i += 256) {
        int j = i/25, dq = i%25;
        ((float4*)(sm + SM_E2))[j*25 + dq] = embE4[(size_t)ids2[j]*25 + dq];
    }
    __syncthreads();
    // M3 = mean over 6 of embO[ids3]  (36 rows)
    for (int i = tid; i < 900; i += 256) {
        int j = i/25, dq = i%25;
        float4 a = embO4[(size_t)ids3[j*6+0]*25 + dq];
        #pragma unroll
        for (int r = 1; r < 6; r++) {
            float4 v = embO4[(size_t)ids3[j*6+r]*25 + dq];
            a.x += v.x; a.y += v.y; a.z += v.z; a.w += v.w;
        }
        const float s6 = 1.f/6.f;
        a.x *= s6; a.y *= s6; a.z *= s6; a.w *= s6;
        ((float4*)(sm + SM_M3))[j*25 + dq] = a;
    }
    __syncthreads();
    // SUM2 = M3 + E2 ; SUM1 = grpmean(E2)+E1 ; S = mean(E1)+E0
    for (int i = tid; i < 3600; i += 256) sm[SM_M3 + i] += sm[SM_E2 + i];
    for (int i = tid; i < 600; i += 256) {
        int r = i/100, d = i%100;
        float s = 0.f;
        #pragma unroll
        for (int j = 0; j < 6; j++) s += sm[SM_E2 + (r*6+j)*100 + d];
        sm[SM_M2 + i] = s * (1.f/6.f) + sm[SM_E1 + i];
    }
    if (tid < 100) {
        float s = 0.f;
        #pragma unroll
        for (int r = 0; r < 6; r++) s += sm[SM_E1 + r*100 + tid];
        sm[SM_S + tid] = s * (1.f/6.f) + sm[SM_E0 + tid];
    }
    __syncthreads();

    const float* w0 = agg_w;           const float* b0 = agg_b;
    const float* w1 = agg_w + 10000;   const float* b1 = agg_b + 100;
    const float* w2 = agg_w + 20000;   const float* b2 = agg_b + 200;
    float* Wt = sm + SM_WT;

    // pass 0
    stage_w(w0, Wt, tid); __syncthreads();
    mm_tanh<1>(sm + SM_S,  1,  Wt, b0, sm + SM_E0B, tid); __syncthreads();
    stage_w(w1, Wt, tid); __syncthreads();
    mm_tanh<2>(sm + SM_M2, 6,  Wt, b1, sm + SM_E1B, tid); __syncthreads();
    stage_w(w2, Wt, tid); __syncthreads();
    mm_tanh<4>(sm + SM_M3, 36, Wt, b2, sm + SM_E2B, tid); __syncthreads();
    // recombine for pass 1
    for (int i = tid; i < 600; i += 256) {
        int r = i/100, d = i%100;
        float s = 0.f;
        #pragma unroll
        for (int j = 0; j < 6; j++) s += sm[SM_E2B + (r*6+j)*100 + d];
        sm[SM_M2 + i] = s * (1.f/6.f) + sm[SM_E1B + i];
    }
    if (tid < 100) {
        float s = 0.f;
        #pragma unroll
        for (int r = 0; r < 6; r++) s += sm[SM_E1B + r*100 + tid];
        sm[SM_S + tid] = s * (1.f/6.f) + sm[SM_E0B + tid];
    }
    __syncthreads();
    stage_w(w0, Wt, tid); __syncthreads();
    mm_tanh<1>(sm + SM_S,  1, Wt, b0, sm + SM_E0, tid); __syncthreads();
    stage_w(w1, Wt, tid); __syncthreads();
    mm_tanh<2>(sm + SM_M2, 6, Wt, b1, sm + SM_E1, tid); __syncthreads();
    // recombine for pass 2
    if (tid < 100) {
        float s = 0.f;
        #pragma unroll
        for (int r = 0; r < 6; r++) s += sm[SM_E1 + r*100 + tid];
        sm[SM_S + tid] = s * (1.f/6.f) + sm[SM_E0 + tid];
    }
    __syncthreads();
    stage_w(w0, Wt, tid); __syncthreads();
    mm_tanh<1>(sm + SM_S, 1, Wt, b0, sm + SM_E0B, tid); __syncthreads();
    // final projection straight to global
    stage_w(W_al, Wt, tid); __syncthreads();
    mm_tanh<1>(sm + SM_E0B, 1, Wt, b_al, outp, tid);
}

// =====================================================================
// k_att: per (t,b): qs rows, ql -> (u, Zq), scores -> top-10 indices
// =====================================================================
__device__ __forceinline__ unsigned long long att_key(float f, int j)
{
    unsigned bb = __float_as_uint(f);
    bb = (bb & 0x80000000u) ? ~bb : (bb | 0x80000000u);
    return ((unsigned long long)bb << 32) | (unsigned)(49 - j);
}

__global__ void k_att(const int* __restrict__ question, const int* __restrict__ qsi,
                      const float* __restrict__ emb_q, const float* __restrict__ emb_s)
{
    __shared__ float qs[5*D_];
    __shared__ float sc[T_];
    __shared__ float qlS[5];
    __shared__ float wqS[5];
    int t = blockIdx.x, b = blockIdx.y;
    int tid = threadIdx.x, lane = tid & 31, w = tid >> 5;
    int qn = question[b*T_ + t + 1];
    const float4* embq4 = (const float4*)emb_q;
    const float4* embs4 = (const float4*)emb_s;

    for (int i = tid; i < 125; i += 256) {
        int row = i/25, dq = i%25;
        float4 v = (row == 0) ? embq4[(size_t)qn*25 + dq]
                              : embs4[(size_t)qsi[qn*4 + row - 1]*25 + dq];
        ((float4*)qs)[i] = v;
    }
    __syncthreads();
    // ql_j = qs_j . vq   (warps 0..4)
    if (w < 5) {
        float s = 0.f;
        for (int d = lane; d < D_; d += 32) s += qs[w*D_ + d] * g_vq[d];
        for (int off = 16; off; off >>= 1) s += __shfl_down_sync(0xffffffffu, s, off);
        if (lane == 0) qlS[w] = s;
    }
    // scores_j = emb_q[question[b,j]] . emb_q[qn]   (all warps)
    for (int j = w; j < T_; j += 8) {
        int qj = question[b*T_ + j];
        float s = 0.f;
        for (int d = lane; d < D_; d += 32) s += emb_q[(size_t)qj*D_ + d] * qs[d];
        for (int off = 16; off; off >>= 1) s += __shfl_down_sync(0xffffffffu, s, off);
        if (lane == 0) sc[j] = (j < t) ? s : NEGF;
    }
    __syncthreads();
    // top-10 (warp 0), ties -> lower index (matches lax.top_k)
    if (w == 0) {
        bool t1 = false, t2 = false;
        int j1 = lane, j2 = lane + 32;
        for (int i = 0; i < 10; i++) {
            unsigned long long k1 = (!t1) ? att_key(sc[j1], j1) : 0ull;
            unsigned long long k2 = (j2 < T_ && !t2) ? att_key(sc[j2], j2) : 0ull;
            unsigned long long mk = k1 > k2 ? k1 : k2;
            for (int off = 16; off; off >>= 1) {
                unsigned long long o = __shfl_xor_sync(0xffffffffu, mk, off);
                if (o > mk) mk = o;
            }
            int jwin = 49 - (int)(mk & 0xffffffffull);
            if (jwin == j1) t1 = true;
            if (jwin == j2) t2 = true;
            if (lane == 0) g_topk[(b*TS_ + t)*10 + i] = (jwin < t) ? jwin : -1;
        }
    }
    __syncthreads();
    if (tid == 0) {
        float mx = qlS[0];
        for (int i = 1; i < 5; i++) mx = fmaxf(mx, qlS[i]);
        float z = 0.f;
        for (int i = 0; i < 5; i++) { wqS[i] = expf(qlS[i] - mx); z += wqS[i]; }
        g_zq[b*TS_ + t] = z;
    }
    __syncthreads();
    if (tid < D_) {
        float u = 0.f;
        #pragma unroll
        for (int j = 0; j < 5; j++) u += wqS[j] * qs[j*D_ + tid];
        g_u[(b*TS_ + t)*D_ + tid] = u;
    }
}

// =====================================================================
// k_fuse: e_t = relu([w1*e1 + w2*e2, emb_r[r]] @ Wf^T + bf)  (16 rows/block)
// =====================================================================
#define FUSE_SM_FLOATS (20200 + 3200)
#define FUSE_SM_BYTES  (FUSE_SM_FLOATS*4)
__global__ __launch_bounds__(256)
void k_fuse(const int* __restrict__ resp, const float* __restrict__ embr,
            const float* __restrict__ w1p, const float* __restrict__ w2p,
            const float* __restrict__ Wf, const float* __restrict__ bf)
{
    extern __shared__ float sm[];
    float* Wt = sm;           // [200][101]
    float* X  = sm + 20200;   // [16][200]
    int tid = threadIdx.x, g0 = blockIdx.x * 16;
    float w1 = *w1p, w2 = *w2p;
    for (int i = tid; i < 20000; i += 256)
        Wt[(i % 200) * 101 + (i / 200)] = Wf[i];
    for (int i = tid; i < 3200; i += 256) {
        int r = i / 200, k = i % 200;
        int g = g0 + r, b = g / TS_, t = g % TS_;
        X[i] = (k < D_)
             ? (w1 * g_e1[g*D_ + k] + w2 * g_e2[g*D_ + k])
             : embr[resp[b*T_ + t]*D_ + (k - D_)];
    }
    __syncthreads();
    for (int task = tid; task < 1600; task += 256) {
        int r = task / D_, o = task % D_;
        float acc = bf[o];
        #pragma unroll 4
        for (int k = 0; k < 200; k++) acc += X[r*200 + k] * Wt[k*101 + o];
        g_et[(g0 + r)*D_ + o] = fmaxf(acc, 0.f);
    }
}

// =====================================================================
// k_ih: G0 = e_t @ W_ih^T + b_ih + b_hh  (16 rows/block)
// =====================================================================
#define IH_SM_FLOATS (40100 + 1600)
#define IH_SM_BYTES  (IH_SM_FLOATS*4)
__global__ __launch_bounds__(256)
void k_ih(const float* __restrict__ Wih, const float* __restrict__ bih,
          const float* __restrict__ bhh)
{
    extern __shared__ float sm[];
    float* Wt = sm;           // [100][401]
    float* X  = sm + 40100;   // [16][100]
    int tid = threadIdx.x, g0 = blockIdx.x * 16;
    for (int i = tid; i < 40000; i += 256)
        Wt[(i % 100) * 401 + (i / 100)] = Wih[i];
    for (int i = tid; i < 1600; i += 256) X[i] = g_et[g0*D_ + i];
    __syncthreads();
    for (int task = tid; task < 6400; task += 256) {
        int r = task / 400, o = task % 400;
        float acc = bih[o] + bhh[o];
        #pragma unroll 4
        for (int k = 0; k < D_; k++) acc += X[r*D_ + k] * Wt[k*401 + o];
        g_preg[(g0 + r)*400 + o] = acc;
    }
}

// =====================================================================
// k_seq: per-batch persistent LSTM + factorized attention
// =====================================================================
#define SQ_W    0         // [100][401] = 40100
#define SQ_SH   40100     // 49*100
#define SQ_GT   45000     // 400
#define SQ_H    45400
#define SQ_C    45500
#define SQ_VK   45600
#define SQ_KLC  45700     // 49 (pad to 52)
#define SQ_WK   45752     // 11 (pad to 16)
#define SQ_INT  45768     // int: idxS[10], maskS[50]
#define SQ_ACC  45828
#define SQ_ZK   45829
#define SEQ_SM_FLOATS 45832
#define SEQ_SM_BYTES  (SEQ_SM_FLOATS*4)

__device__ __forceinline__ float sigf(float x) { return 1.f/(1.f + expf(-x)); }

__global__ __launch_bounds__(256, 1)
void k_seq(const int* __restrict__ mask, const float* __restrict__ Whh,
           float* __restrict__ out)
{
    extern __shared__ float sm[];
    float* W     = sm + SQ_W;
    float* sh    = sm + SQ_SH;
    float* gates = sm + SQ_GT;
    float* h     = sm + SQ_H;
    float* c     = sm + SQ_C;
    float* vk    = sm + SQ_VK;
    float* klc   = sm + SQ_KLC;
    float* wk    = sm + SQ_WK;
    int*   idxS  = (int*)(sm + SQ_INT);
    int*   maskS = idxS + 10;

    int b = blockIdx.x, tid = threadIdx.x;
    for (int i = tid; i < 40000; i += 256)
        W[(i % 100) * 401 + (i / 100)] = Whh[i];
    if (tid < D_) { h[tid] = 0.f; c[tid] = 0.f; vk[tid] = g_vk[tid]; }
    if (tid < T_) maskS[tid] = mask[b*T_ + tid];
    if (tid == 0) out[b*T_] = 0.5f;
    __syncthreads();

    for (int t = 0; t < TS_; t++) {
        // gates = G0 + h @ Whh^T
        const float* G0 = g_preg + (size_t)(b*TS_ + t) * 400;
        {
            float a1 = G0[tid];
            #pragma unroll 4
            for (int k = 0; k < D_; k++) a1 += h[k] * W[k*401 + tid];
            gates[tid] = a1;
            int o2 = tid + 256;
            if (o2 < 400) {
                float a2 = G0[o2];
                #pragma unroll 4
                for (int k = 0; k < D_; k++) a2 += h[k] * W[k*401 + o2];
                gates[o2] = a2;
            }
        }
        __syncthreads();
        // LSTM pointwise + store history
        if (tid < D_) {
            float gi = gates[tid], gf = gates[D_ + tid];
            float gg = gates[2*D_ + tid], go = gates[3*D_ + tid];
            float c2 = sigf(gf) * c[tid] + sigf(gi) * tanhf(gg);
            float h2 = sigf(go) * tanhf(c2);
            if (maskS[t]) { h[tid] = h2; c[tid] = c2; }
            sh[t*D_ + tid] = h[tid];
        }
        __syncthreads();
        // kl for current h; attention scalar prep (thread 0)
        if (tid < 32) {
            float s = 0.f;
            for (int d = tid; d < D_; d += 32) s += h[d] * vk[d];
            for (int off = 16; off; off >>= 1) s += __shfl_down_sync(0xffffffffu, s, off);
            if (tid == 0) {
                klc[t] = s;
                const int* ix = g_topk + (b*TS_ + t) * 10;
                int loc[10];
                float mx = s;
                #pragma unroll
                for (int i = 0; i < 10; i++) {
                    loc[i] = ix[i];
                    if (loc[i] >= 0) mx = fmaxf(mx, klc[loc[i]]);
                }
                float zk = expf(s - mx);
                wk[0] = zk;
                #pragma unroll
                for (int i = 0; i < 10; i++) {
                    float ww = (loc[i] >= 0) ? expf(klc[loc[i]] - mx) : 0.f;
                    wk[i+1] = ww; zk += ww; idxS[i] = loc[i];
                }
                sm[SQ_ZK] = zk;
                sm[SQ_ACC] = 0.f;
            }
        }
        __syncthreads();
        // v = sum_s wk_s * state_s ;  y = sigmoid( (u.v) / (Zq*Zk) )
        float pv = 0.f;
        if (tid < D_) {
            float vd = wk[0] * h[tid];
            #pragma unroll
            for (int i = 0; i < 10; i++) {
                int id = idxS[i];
                if (id >= 0) vd += wk[i+1] * sh[id*D_ + tid];
            }
            pv = g_u[(size_t)(b*TS_ + t)*D_ + tid] * vd;
        }
        for (int off = 16; off; off >>= 1) pv += __shfl_down_sync(0xffffffffu, pv, off);
        if ((tid & 31) == 0) atomicAdd(&sm[SQ_ACC], pv);
        __syncthreads();
        if (tid == 0) {
            float y = sm[SQ_ACC] / (g_zq[b*TS_ + t] * sm[SQ_ZK]);
            out[b*T_ + t + 1] = 1.f / (1.f + expf(-y));
        }
        __syncthreads();
    }
}

// =====================================================================
// launch
// =====================================================================
extern "C" void kernel_launch(void* const* d_in, const int* in_sizes, int n_in,
                              void* d_out, int out_size)
{
    const int*   user      = (const int*)  d_in[0];
    const int*   question  = (const int*)  d_in[1];
    const int*   response  = (const int*)  d_in[2];
    const int*   mask      = (const int*)  d_in[3];
    const int*   q_nb      = (const int*)  d_in[4];
    const int*   s_nb      = (const int*)  d_in[5];
    const int*   u_nb      = (const int*)  d_in[6];
    const int*   q_nb2     = (const int*)  d_in[7];
    const int*   qsi       = (const int*)  d_in[8];
    const float* emb_q     = (const float*)d_in[9];
    const float* emb_q2    = (const float*)d_in[10];
    const float* emb_s     = (const float*)d_in[11];
    const float* emb_u     = (const float*)d_in[12];
    const float* emb_r     = (const float*)d_in[13];
    const float* w1p       = (const float*)d_in[14];
    const float* w2p       = (const float*)d_in[15];
    const float* W_ih      = (const float*)d_in[16];
    const float* W_hh      = (const float*)d_in[17];
    const float* b_ih      = (const float*)d_in[18];
    const float* b_hh      = (const float*)d_in[19];
    const float* agg_w     = (const float*)d_in[20];
    const float* agg_b     = (const float*)d_in[21];
    const float* W_al      = (const float*)d_in[22];
    const float* b_al      = (const float*)d_in[23];
    const float* W_q       = (const float*)d_in[24];
    const float* W_k       = (const float*)d_in[26];
    const float* W_w       = (const float*)d_in[28];
    const float* W_f       = (const float*)d_in[30];
    const float* b_f       = (const float*)d_in[31];
    float* out = (float*)d_out;
    (void)in_sizes; (void)n_in; (void)out_size;

    cudaFuncSetAttribute(k_agg,  cudaFuncAttributeMaxDynamicSharedMemorySize, AGG_SM_BYTES);
    cudaFuncSetAttribute(k_fuse, cudaFuncAttributeMaxDynamicSharedMemorySize, FUSE_SM_BYTES);
    cudaFuncSetAttribute(k_ih,   cudaFuncAttributeMaxDynamicSharedMemorySize, IH_SM_BYTES);
    cudaFuncSetAttribute(k_seq,  cudaFuncAttributeMaxDynamicSharedMemorySize, SEQ_SM_BYTES);

    k_prep<<<1, 128>>>(W_q, W_k, W_w);
    k_agg<<<dim3(TS_, B_, 2), 256, AGG_SM_BYTES>>>(question, user, mask,
        q_nb, s_nb, u_nb, q_nb2, emb_q, emb_q2, emb_s, emb_u,
        agg_w, agg_b, W_al, b_al);
    k_att<<<dim3(TS_, B_), 256>>>(question, qsi, emb_q, emb_s);
    k_fuse<<<98, 256, FUSE_SM_BYTES>>>(response, emb_r, w1p, w2p, W_f, b_f);
    k_ih<<<98, 256, IH_SM_BYTES>>>(W_ih, b_ih, b_hh);
    k_seq<<<B_, 256, SEQ_SM_BYTES>>>(mask, W_hh, out);
}

// round 7
// speedup vs baseline: 1.1111x; 1.1111x over previous
#include <cuda_runtime.h>
#include <cuda_bf16.h>
#include <math.h>

#define B_   32
#define T_   50
#define TS_  49
#define D_   100
#define NEGF (-1000000000.0f)
#define NROW (B_*TS_)   // 1568
#define NITEM (NROW*2)  // 3136

// ---------------- device scratch ----------------
__device__ float g_e1[NROW*D_];
__device__ float g_e2[NROW*D_];
__device__ float g_et[NROW*D_];
__device__ float g_preg[NROW*400];
__device__ float g_u[NROW*D_];
__device__ float g_zq[NROW];
__device__ int   g_topk[NROW*10];
__device__ float g_vq[D_];
__device__ float g_vk[D_];
__device__ int   g_ctr;

// =====================================================================
// k_prep: vq = W_query^T wA, vk = W_key^T wB ; reset work-queue counter
// =====================================================================
__global__ void k_prep(const float* __restrict__ Wq, const float* __restrict__ Wk,
                       const float* __restrict__ Ww)
{
    int d = threadIdx.x;
    if (d < D_) {
        float a = 0.f, c = 0.f;
        for (int e = 0; e < D_; e++) {
            a += Ww[e]       * Wq[e*D_ + d];
            c += Ww[D_ + e]  * Wk[e*D_ + d];
        }
        g_vq[d] = a; g_vk[d] = c;
    }
    if (d == 112) g_ctr = 0;
}

// =====================================================================
// mm_tile: one (RT rows x 4 cols) tile of tanh(X @ W^T + b)
// Wt transposed [k*101 + o]; cols cq, cq+25, cq+50, cq+75.
// =====================================================================
template<int RT>
__device__ __forceinline__ void mm_tile(const float* __restrict__ X,
                                        const float* __restrict__ Wt,
                                        const float* __restrict__ bias,
                                        float* __restrict__ out, int cq)
{
    float acc[RT][4];
    #pragma unroll
    for (int r = 0; r < RT; r++) { acc[r][0]=0.f; acc[r][1]=0.f; acc[r][2]=0.f; acc[r][3]=0.f; }
    #pragma unroll 4
    for (int k = 0; k < D_; k++) {
        const float* wr = Wt + k*101 + cq;
        float w0 = wr[0], w1 = wr[25], w2 = wr[50], w3 = wr[75];
        #pragma unroll
        for (int r = 0; r < RT; r++) {
            float x = X[r*D_ + k];
            acc[r][0] += x*w0; acc[r][1] += x*w1; acc[r][2] += x*w2; acc[r][3] += x*w3;
        }
    }
    float b0 = __ldg(bias+cq), b1 = __ldg(bias+cq+25), b2 = __ldg(bias+cq+50), b3 = __ldg(bias+cq+75);
    #pragma unroll
    for (int r = 0; r < RT; r++) {
        float* o = out + r*D_ + cq;
        o[0]  = tanhf(acc[r][0] + b0);
        o[25] = tanhf(acc[r][1] + b1);
        o[50] = tanhf(acc[r][2] + b2);
        o[75] = tanhf(acc[r][3] + b3);
    }
}

// =====================================================================
// k_agg: grid 148, weights resident, atomic work queue over 3136 items
// =====================================================================
#define AGG_WT  0
#define AGG_A   40400
#define AGG_B   44000
#define AGG_C   47600
#define AGG_D   48200
#define AGG_E0A 48800
#define AGG_E0B 48900
#define AGG_IDS 49000
#define AGG_SM_FLOATS 49264
#define AGG_SM_BYTES  (AGG_SM_FLOATS*4)

__global__ __launch_bounds__(256, 1)
void k_agg(const int* __restrict__ question, const int* __restrict__ user,
           const int* __restrict__ mask,
           const int* __restrict__ q_nb, const int* __restrict__ s_nb,
           const int* __restrict__ u_nb, const int* __restrict__ q_nb2,
           const float* __restrict__ emb_q, const float* __restrict__ emb_q2,
           const float* __restrict__ emb_s, const float* __restrict__ emb_u,
           const float* __restrict__ agg_w, const float* __restrict__ agg_b,
           const float* __restrict__ W_al,  const float* __restrict__ b_al)
{
    extern __shared__ float sm[];
    float* WT  = sm + AGG_WT;
    float* A   = sm + AGG_A;
    float* Bb  = sm + AGG_B;
    float* C   = sm + AGG_C;
    float* Dd  = sm + AGG_D;
    float* E0A = sm + AGG_E0A;
    float* E0B = sm + AGG_E0B;
    int*   ids = (int*)(sm + AGG_IDS);
    int*   ids2 = ids + 6;
    int*   ids3 = ids + 42;
    int*   s_item = ids + 258;
    int tid = threadIdx.x;

    // stage all four weights, transposed (write stride 101 -> conflict-free)
    for (int i = tid; i < 10000; i += 256) {
        int o = i / 100, k = i % 100;
        int s = k*101 + o;
        WT[s]         = agg_w[i];
        WT[10100 + s] = agg_w[10000 + i];
        WT[20200 + s] = agg_w[20000 + i];
        WT[30300 + s] = W_al[i];
    }

    float4* A4 = (float4*)A; float4* B4 = (float4*)Bb;
    float4* C4 = (float4*)C; float4* D4 = (float4*)Dd;
    float4* E0A4 = (float4*)E0A; float4* E0B4 = (float4*)E0B;

    for (;;) {
        __syncthreads();
        if (tid == 0) *s_item = atomicAdd(&g_ctr, 1);
        __syncthreads();
        int item = *s_item;
        if (item >= NITEM) break;
        int side = item & 1, pair = item >> 1;
        int b = pair / TS_, t = pair % TS_;
        int m  = mask[b*T_ + t];
        int qt = question[b*T_ + t];
        float* outp = (side == 0 ? g_e1 : g_e2) + pair * D_;

        if (!m) {
            if (tid < 25) {
                const float4* src = (const float4*)((side == 0 ? emb_q : emb_q2) + (size_t)qt*D_);
                ((float4*)outp)[tid] = src[tid];
            }
            continue;
        }

        int n0; const int *tabE, *tabO; const float *embE, *embO;
        if (side == 0) { n0 = qt;           tabE = q_nb; tabO = s_nb;  embE = emb_q; embO = emb_s;  }
        else           { n0 = user[b*T_+t]; tabE = u_nb; tabO = q_nb2; embE = emb_u; embO = emb_q2; }
        const float4* embE4 = (const float4*)embE;
        const float4* embO4 = (const float4*)embO;

        if (tid < 6) ids[tid] = tabE[n0*6 + tid];
        if (tid >= 64 && tid < 89) E0A4[tid-64] = embE4[(size_t)n0*25 + (tid-64)];
        __syncthreads();
        if (tid < 36) ids2[tid] = tabO[ids[tid/6]*6 + tid%6];
        __syncthreads();
        if (tid < 216) ids3[tid] = tabE[ids2[tid/6]*6 + tid%6];
        // B <- E2 gather (36 rows)
        for (int i = tid; i < 900; i += 256) {
            int j = i/25, dq = i%25;
            B4[i] = embE4[(size_t)ids2[j]*25 + dq];
        }
        __syncthreads();
        // A <- mean6(E3)+B ; C <- grpmean6(B)+E1 ; E0A += mean(E1)
        for (int i = tid; i < 1075; i += 256) {
            if (i < 900) {
                int j = i/25, dq = i%25;
                float4 a = embO4[(size_t)ids3[j*6+0]*25 + dq];
                #pragma unroll
                for (int r = 1; r < 6; r++) {
                    float4 v = embO4[(size_t)ids3[j*6+r]*25 + dq];
                    a.x += v.x; a.y += v.y; a.z += v.z; a.w += v.w;
                }
                const float s6 = 1.f/6.f;
                float4 bb = B4[i];
                a.x = a.x*s6 + bb.x; a.y = a.y*s6 + bb.y;
                a.z = a.z*s6 + bb.z; a.w = a.w*s6 + bb.w;
                A4[i] = a;
            } else if (i < 1050) {
                int u = i - 900; int r = u/25, dq = u%25;
                float4 s = B4[(r*6+0)*25 + dq];
                #pragma unroll
                for (int j = 1; j < 6; j++) {
                    float4 v = B4[(r*6+j)*25 + dq];
                    s.x += v.x; s.y += v.y; s.z += v.z; s.w += v.w;
                }
                const float s6 = 1.f/6.f;
                float4 e = embO4[(size_t)ids[r]*25 + dq];
                s.x = s.x*s6 + e.x; s.y = s.y*s6 + e.y;
                s.z = s.z*s6 + e.z; s.w = s.w*s6 + e.w;
                C4[u] = s;
            } else {
                int dq = i - 1050;
                float4 s = embO4[(size_t)ids[0]*25 + dq];
                #pragma unroll
                for (int j = 1; j < 6; j++) {
                    float4 v = embO4[(size_t)ids[j]*25 + dq];
                    s.x += v.x; s.y += v.y; s.z += v.z; s.w += v.w;
                }
                const float s6 = 1.f/6.f;
                float4 e = E0A4[dq];
                e.x += s.x*s6; e.y += s.y*s6; e.z += s.z*s6; e.w += s.w*s6;
                E0A4[dq] = e;
            }
        }
        __syncthreads();
        // pass0: fused across the three levels (all weights resident)
        for (int task = tid; task < 325; task += 256) {
            if (task < 25)       mm_tile<1>(E0A, WT, agg_b, E0B, task);
            else if (task < 100) { int u = task-25;  mm_tile<2>(C + (u/25)*200, WT+10100, agg_b+100, Dd + (u/25)*200, u%25); }
            else                 { int u = task-100; mm_tile<4>(A + (u/25)*400, WT+20200, agg_b+200, Bb + (u/25)*400, u%25); }
        }
        __syncthreads();
        // recombine: C' = grpmean(B)+D ; E0A = mean(D)+E0B
        for (int i = tid; i < 175; i += 256) {
            if (i < 150) {
                int r = i/25, dq = i%25;
                float4 s = B4[(r*6+0)*25 + dq];
                #pragma unroll
                for (int j = 1; j < 6; j++) {
                    float4 v = B4[(r*6+j)*25 + dq];
                    s.x += v.x; s.y += v.y; s.z += v.z; s.w += v.w;
                }
                const float s6 = 1.f/6.f;
                float4 d = D4[i];
                s.x = s.x*s6 + d.x; s.y = s.y*s6 + d.y;
                s.z = s.z*s6 + d.z; s.w = s.w*s6 + d.w;
                C4[i] = s;
            } else {
                int dq = i - 150;
                float4 s = D4[dq];
                #pragma unroll
                for (int j = 1; j < 6; j++) {
                    float4 v = D4[j*25 + dq];
                    s.x += v.x; s.y += v.y; s.z += v.z; s.w += v.w;
                }
                const float s6 = 1.f/6.f;
                float4 e = E0B4[dq];
                e.x += s.x*s6; e.y += s.y*s6; e.z += s.z*s6; e.w += s.w*s6;
                E0A4[dq] = e;
            }
        }
        __syncthreads();
        // pass1
        for (int task = tid; task < 100; task += 256) {
            if (task < 25) mm_tile<1>(E0A, WT, agg_b, E0B, task);
            else { int u = task-25; mm_tile<2>(C + (u/25)*200, WT+10100, agg_b+100, Dd + (u/25)*200, u%25); }
        }
        __syncthreads();
        // recombine: E0A = mean(D) + E0B
        if (tid < 25) {
            float4 s = D4[tid];
            #pragma unroll
            for (int j = 1; j < 6; j++) {
                float4 v = D4[j*25 + tid];
                s.x += v.x; s.y += v.y; s.z += v.z; s.w += v.w;
            }
            const float s6 = 1.f/6.f;
            float4 e = E0B4[tid];
            e.x += s.x*s6; e.y += s.y*s6; e.z += s.z*s6; e.w += s.w*s6;
            E0A4[tid] = e;
        }
        __syncthreads();
        // pass2
        for (int task = tid; task < 25; task += 256) mm_tile<1>(E0A, WT, agg_b, E0B, task);
        __syncthreads();
        // final projection straight to global
        for (int task = tid; task < 25; task += 256) mm_tile<1>(E0B, WT+30300, b_al, outp, task);
    }
}

// =====================================================================
// k_att: per (t,b): qs rows, ql -> (u, Zq), scores -> top-10 indices
// =====================================================================
__device__ __forceinline__ unsigned long long att_key(float f, int j)
{
    unsigned bb = __float_as_uint(f);
    bb = (bb & 0x80000000u) ? ~bb : (bb | 0x80000000u);
    return ((unsigned long long)bb << 32) | (unsigned)(49 - j);
}

__global__ void k_att(const int* __restrict__ question, const int* __restrict__ qsi,
                      const float* __restrict__ emb_q, const float* __restrict__ emb_s)
{
    __shared__ float qs[5*D_];
    __shared__ float sc[T_];
    __shared__ float qlS[5];
    __shared__ float wqS[5];
    int t = blockIdx.x, b = blockIdx.y;
    int tid = threadIdx.x, lane = tid & 31, w = tid >> 5;
    int qn = question[b*T_ + t + 1];
    const float4* embq4 = (const float4*)emb_q;
    const float4* embs4 = (const float4*)emb_s;

    for (int i = tid; i < 125; i += 256) {
        int row = i/25, dq = i%25;
        float4 v = (row == 0) ? embq4[(size_t)qn*25 + dq]
                              : embs4[(size_t)qsi[qn*4 + row - 1]*25 + dq];
        ((float4*)qs)[i] = v;
    }
    __syncthreads();
    if (w < 5) {
        float s = 0.f;
        for (int d = lane; d < D_; d += 32) s += qs[w*D_ + d] * g_vq[d];
        for (int off = 16; off; off >>= 1) s += __shfl_down_sync(0xffffffffu, s, off);
        if (lane == 0) qlS[w] = s;
    }
    for (int j = w; j < T_; j += 8) {
        int qj = question[b*T_ + j];
        float s = 0.f;
        for (int d = lane; d < D_; d += 32) s += emb_q[(size_t)qj*D_ + d] * qs[d];
        for (int off = 16; off; off >>= 1) s += __shfl_down_sync(0xffffffffu, s, off);
        if (lane == 0) sc[j] = (j < t) ? s : NEGF;
    }
    __syncthreads();
    if (w == 0) {
        bool t1 = false, t2 = false;
        int j1 = lane, j2 = lane + 32;
        for (int i = 0; i < 10; i++) {
            unsigned long long k1 = (!t1) ? att_key(sc[j1], j1) : 0ull;
            unsigned long long k2 = (j2 < T_ && !t2) ? att_key(sc[j2], j2) : 0ull;
            unsigned long long mk = k1 > k2 ? k1 : k2;
            for (int off = 16; off; off >>= 1) {
                unsigned long long o = __shfl_xor_sync(0xffffffffu, mk, off);
                if (o > mk) mk = o;
            }
            int jwin = 49 - (int)(mk & 0xffffffffull);
            if (jwin == j1) t1 = true;
            if (jwin == j2) t2 = true;
            if (lane == 0) g_topk[(b*TS_ + t)*10 + i] = (jwin < t) ? jwin : -1;
        }
    }
    __syncthreads();
    if (tid == 0) {
        float mx = qlS[0];
        for (int i = 1; i < 5; i++) mx = fmaxf(mx, qlS[i]);
        float z = 0.f;
        for (int i = 0; i < 5; i++) { wqS[i] = expf(qlS[i] - mx); z += wqS[i]; }
        g_zq[b*TS_ + t] = z;
    }
    __syncthreads();
    if (tid < D_) {
        float u = 0.f;
        #pragma unroll
        for (int j = 0; j < 5; j++) u += wqS[j] * qs[j*D_ + tid];
        g_u[(b*TS_ + t)*D_ + tid] = u;
    }
}

// =====================================================================
// k_fuse: e_t = relu([w1*e1+w2*e2, emb_r] @ Wf^T + bf); 8 rows/block, grid 196
// =====================================================================
__global__ __launch_bounds__(256, 2)
void k_fuse(const int* __restrict__ resp, const float* __restrict__ embr,
            const float* __restrict__ w1p, const float* __restrict__ w2p,
            const float* __restrict__ Wf, const float* __restrict__ bf)
{
    __shared__ float Wt[20200];     // [200][101]
    __shared__ float X[8*200];
    int tid = threadIdx.x, g0 = blockIdx.x * 8;
    float w1 = *w1p, w2 = *w2p;
    for (int i = tid; i < 20000; i += 256)
        Wt[(i % 200)*101 + (i / 200)] = Wf[i];
    for (int i = tid; i < 1600; i += 256) {
        int r = i / 200, k = i % 200;
        int g = g0 + r, b = g / TS_, t = g % TS_;
        X[i] = (k < D_)
             ? (w1 * g_e1[g*D_ + k] + w2 * g_e2[g*D_ + k])
             : embr[resp[b*T_ + t]*D_ + (k - D_)];
    }
    __syncthreads();
    // RT2 x CT2 -> 200 tasks
    for (int task = tid; task < 200; task += 256) {
        int rg = task / 50, cq = task % 50;
        const float* Xb = X + rg*400;
        float a00=0.f, a01=0.f, a10=0.f, a11=0.f;
        #pragma unroll 4
        for (int k = 0; k < 200; k++) {
            float wv0 = Wt[k*101 + cq], wv1 = Wt[k*101 + cq + 50];
            float x0 = Xb[k], x1 = Xb[200 + k];
            a00 += x0*wv0; a01 += x0*wv1; a10 += x1*wv0; a11 += x1*wv1;
        }
        float b0 = __ldg(bf+cq), b1 = __ldg(bf+cq+50);
        int r0 = g0 + rg*2;
        g_et[r0*D_ + cq]          = fmaxf(a00 + b0, 0.f);
        g_et[r0*D_ + cq + 50]     = fmaxf(a01 + b1, 0.f);
        g_et[(r0+1)*D_ + cq]      = fmaxf(a10 + b0, 0.f);
        g_et[(r0+1)*D_ + cq + 50] = fmaxf(a11 + b1, 0.f);
    }
}

// =====================================================================
// k_ih: G0 = e_t @ W_ih^T + b_ih + b_hh; 8 rows/block, grid 196
// =====================================================================
#define IH_SM_FLOATS (40100 + 800)
#define IH_SM_BYTES  (IH_SM_FLOATS*4)
__global__ __launch_bounds__(256, 1)
void k_ih(const float* __restrict__ Wih, const float* __restrict__ bih,
          const float* __restrict__ bhh)
{
    extern __shared__ float sm[];
    float* Wt = sm;          // [100][401]
    float* X  = sm + 40100;  // [8][100]
    int tid = threadIdx.x, g0 = blockIdx.x * 8;
    for (int i = tid; i < 40000; i += 256)
        Wt[(i % 100)*401 + (i / 100)] = Wih[i];
    for (int i = tid; i < 800; i += 256) X[i] = g_et[g0*D_ + i];
    __syncthreads();
    // RT2 x CT4 over 400 cols -> 400 tasks
    for (int task = tid; task < 400; task += 256) {
        int rg = task / 100, cq = task % 100;
        const float* Xb = X + rg*200;
        float a[2][4];
        #pragma unroll
        for (int r = 0; r < 2; r++) { a[r][0]=0.f; a[r][1]=0.f; a[r][2]=0.f; a[r][3]=0.f; }
        #pragma unroll 4
        for (int k = 0; k < D_; k++) {
            const float* wr = Wt + k*401 + cq;
            float w0 = wr[0], w1 = wr[100], w2 = wr[200], w3 = wr[300];
            float x0 = Xb[k], x1 = Xb[100 + k];
            a[0][0]+=x0*w0; a[0][1]+=x0*w1; a[0][2]+=x0*w2; a[0][3]+=x0*w3;
            a[1][0]+=x1*w0; a[1][1]+=x1*w1; a[1][2]+=x1*w2; a[1][3]+=x1*w3;
        }
        #pragma unroll
        for (int r = 0; r < 2; r++) {
            int row = g0 + rg*2 + r;
            #pragma unroll
            for (int c = 0; c < 4; c++) {
                int o = cq + c*100;
                g_preg[row*400 + o] = a[r][c] + __ldg(bih+o) + __ldg(bhh+o);
            }
        }
    }
}

// =====================================================================
// k_seq: per-batch persistent LSTM, W_hh in registers (800 threads)
// =====================================================================
__device__ __forceinline__ float sigf(float x) { return 1.f/(1.f + expf(-x)); }

__global__ __launch_bounds__(800, 1)
void k_seq(const int* __restrict__ mask, const float* __restrict__ Whh,
           float* __restrict__ out)
{
    __shared__ float sh[TS_*D_];
    __shared__ float pp[800];
    __shared__ float gates[400];
    __shared__ float h[D_], c[D_], vk[D_];
    __shared__ float klc[TS_];
    __shared__ float wk[11];
    __shared__ float sACC, sZK;
    __shared__ int idxS[10], maskS[T_];

    int b = blockIdx.x, tid = threadIdx.x;
    int o = tid >> 1, half = tid & 1;

    // Each thread holds half a W_hh row in registers (52 / 48 floats)
    float4 w[13];
    {
        const float4* Wr = (const float4*)(Whh + o*D_ + half*52);
        #pragma unroll
        for (int j = 0; j < 13; j++)
            if (half == 0 || j < 12) w[j] = __ldg(Wr + j);
    }
    if (tid < D_) { h[tid] = 0.f; c[tid] = 0.f; vk[tid] = g_vk[tid]; }
    if (tid < T_) maskS[tid] = mask[b*T_ + tid];
    if (tid == 0) out[b*T_] = 0.5f;
    __syncthreads();

    for (int t = 0; t < TS_; t++) {
        const float* G0 = g_preg + (size_t)(b*TS_ + t) * 400;
        // partial GEMV: pp[tid] = dot(w, h-half)
        {
            float acc = 0.f;
            const float4* h4 = (const float4*)h;
            if (half == 0) {
                #pragma unroll
                for (int j = 0; j < 13; j++) {
                    float4 hv = h4[j];
                    acc += w[j].x*hv.x + w[j].y*hv.y + w[j].z*hv.z + w[j].w*hv.w;
                }
            } else {
                #pragma unroll
                for (int j = 0; j < 12; j++) {
                    float4 hv = h4[13 + j];
                    acc += w[j].x*hv.x + w[j].y*hv.y + w[j].z*hv.z + w[j].w*hv.w;
                }
            }
            pp[tid] = acc;
        }
        __syncthreads();
        if (tid < 400) gates[tid] = G0[tid] + pp[2*tid] + pp[2*tid+1];
        __syncthreads();
        if (tid < D_) {
            float gi = gates[tid], gf = gates[D_ + tid];
            float gg = gates[2*D_ + tid], go = gates[3*D_ + tid];
            float c2 = sigf(gf) * c[tid] + sigf(gi) * tanhf(gg);
            float h2 = sigf(go) * tanhf(c2);
            if (maskS[t]) { h[tid] = h2; c[tid] = c2; }
            sh[t*D_ + tid] = h[tid];
        }
        __syncthreads();
        if (tid < 32) {
            float s = 0.f;
            for (int d = tid; d < D_; d += 32) s += h[d] * vk[d];
            for (int off = 16; off; off >>= 1) s += __shfl_down_sync(0xffffffffu, s, off);
            if (tid == 0) {
                klc[t] = s;
                const int* ix = g_topk + (b*TS_ + t) * 10;
                int loc[10];
                float mx = s;
                #pragma unroll
                for (int i = 0; i < 10; i++) {
                    loc[i] = ix[i];
                    if (loc[i] >= 0) mx = fmaxf(mx, klc[loc[i]]);
                }
                float zk = expf(s - mx);
                wk[0] = zk;
                #pragma unroll
                for (int i = 0; i < 10; i++) {
                    float ww = (loc[i] >= 0) ? expf(klc[loc[i]] - mx) : 0.f;
                    wk[i+1] = ww; zk += ww; idxS[i] = loc[i];
                }
                sZK = zk;
                sACC = 0.f;
            }
        }
        __syncthreads();
        float pv = 0.f;
        if (tid < D_) {
            float vd = wk[0] * h[tid];
            #pragma unroll
            for (int i = 0; i < 10; i++) {
                int id = idxS[i];
                if (id >= 0) vd += wk[i+1] * sh[id*D_ + tid];
            }
            pv = g_u[(size_t)(b*TS_ + t)*D_ + tid] * vd;
        }
        if (tid < 128) {
            for (int off = 16; off; off >>= 1) pv += __shfl_down_sync(0xffffffffu, pv, off);
            if ((tid & 31) == 0) atomicAdd(&sACC, pv);
        }
        __syncthreads();
        if (tid == 0) {
            float y = sACC / (g_zq[b*TS_ + t] * sZK);
            out[b*T_ + t + 1] = 1.f / (1.f + expf(-y));
        }
        __syncthreads();
    }
}

// =====================================================================
// launch
// =====================================================================
extern "C" void kernel_launch(void* const* d_in, const int* in_sizes, int n_in,
                              void* d_out, int out_size)
{
    const int*   user      = (const int*)  d_in[0];
    const int*   question  = (const int*)  d_in[1];
    const int*   response  = (const int*)  d_in[2];
    const int*   mask      = (const int*)  d_in[3];
    const int*   q_nb      = (const int*)  d_in[4];
    const int*   s_nb      = (const int*)  d_in[5];
    const int*   u_nb      = (const int*)  d_in[6];
    const int*   q_nb2     = (const int*)  d_in[7];
    const int*   qsi       = (const int*)  d_in[8];
    const float* emb_q     = (const float*)d_in[9];
    const float* emb_q2    = (const float*)d_in[10];
    const float* emb_s     = (const float*)d_in[11];
    const float* emb_u     = (const float*)d_in[12];
    const float* emb_r     = (const float*)d_in[13];
    const float* w1p       = (const float*)d_in[14];
    const float* w2p       = (const float*)d_in[15];
    const float* W_ih      = (const float*)d_in[16];
    const float* W_hh      = (const float*)d_in[17];
    const float* b_ih      = (const float*)d_in[18];
    const float* b_hh      = (const float*)d_in[19];
    const float* agg_w     = (const float*)d_in[20];
    const float* agg_b     = (const float*)d_in[21];
    const float* W_al      = (const float*)d_in[22];
    const float* b_al      = (const float*)d_in[23];
    const float* W_q       = (const float*)d_in[24];
    const float* W_k       = (const float*)d_in[26];
    const float* W_w       = (const float*)d_in[28];
    const float* W_f       = (const float*)d_in[30];
    const float* b_f       = (const float*)d_in[31];
    float* out = (float*)d_out;
    (void)in_sizes; (void)n_in; (void)out_size;

    cudaFuncSetAttribute(k_agg, cudaFuncAttributeMaxDynamicSharedMemorySize, AGG_SM_BYTES);
    cudaFuncSetAttribute(k_ih,  cudaFuncAttributeMaxDynamicSharedMemorySize, IH_SM_BYTES);

    k_prep<<<1, 128>>>(W_q, W_k, W_w);
    k_agg<<<148, 256, AGG_SM_BYTES>>>(question, user, mask,
        q_nb, s_nb, u_nb, q_nb2, emb_q, emb_q2, emb_s, emb_u,
        agg_w, agg_b, W_al, b_al);
    k_att<<<dim3(TS_, B_), 256>>>(question, qsi, emb_q, emb_s);
    k_fuse<<<196, 256>>>(response, emb_r, w1p, w2p, W_f, b_f);
    k_ih<<<196, 256, IH_SM_BYTES>>>(W_ih, b_ih, b_hh);
    k_seq<<<B_, 800>>>(mask, W_hh, out);
}

// round 9
// speedup vs baseline: 1.7660x; 1.5894x over previous
#include <cuda_runtime.h>
#include <cuda_bf16.h>
#include <math.h>

#define B_   32
#define T_   50
#define TS_  49
#define D_   100
#define NEGF (-1000000000.0f)
#define NROW (B_*TS_)   // 1568
#define NITEM (NROW*2)  // 3136

// ---------------- device scratch ----------------
__device__ float g_e1[NROW*D_];
__device__ float g_e2[NROW*D_];
__device__ float g_et[NROW*D_];
__device__ float g_preg[NROW*400];
__device__ float g_u[NROW*D_];
__device__ float g_zq[NROW];
__device__ float g_sh[NROW*D_];
__device__ int   g_topk[NROW*10];
__device__ float g_vq[D_];
__device__ float g_vk[D_];
__device__ int   g_ctr;

// ---------------- fast activations (err ~1e-6, MUFU-based) ----------------
__device__ __forceinline__ float fast_sig(float x)  { return __fdividef(1.f, 1.f + __expf(-x)); }
__device__ __forceinline__ float fast_tanh(float x) { return 1.f - __fdividef(2.f, __expf(2.f*x) + 1.f); }

__device__ __forceinline__ void fma4(float4& a, float x, const float4& w) {
    a.x += x*w.x; a.y += x*w.y; a.z += x*w.z; a.w += x*w.w;
}
__device__ __forceinline__ float4 tanh4b(const float4& a, const float4& b) {
    float4 r;
    r.x = fast_tanh(a.x + b.x); r.y = fast_tanh(a.y + b.y);
    r.z = fast_tanh(a.z + b.z); r.w = fast_tanh(a.w + b.w);
    return r;
}

// =====================================================================
// k_prep
// =====================================================================
__global__ void k_prep(const float* __restrict__ Wq, const float* __restrict__ Wk,
                       const float* __restrict__ Ww)
{
    int d = threadIdx.x;
    if (d < D_) {
        float a = 0.f, c = 0.f;
        for (int e = 0; e < D_; e++) {
            a += Ww[e]       * Wq[e*D_ + d];
            c += Ww[D_ + e]  * Wk[e*D_ + d];
        }
        g_vq[d] = a; g_vk[d] = c;
    }
    if (d == 112) g_ctr = 0;
}

// =====================================================================
// mm cores: X k-major (stride xs), W k-major (stride ws), K k-steps
// =====================================================================
__device__ __forceinline__ void mm4_core(const float* __restrict__ Xt, int xs, int xoff,
                                         const float* __restrict__ Wt, int ws, int wo, int K,
                                         float4& a0, float4& a1, float4& a2, float4& a3)
{
    #pragma unroll 4
    for (int k = 0; k < K; k++) {
        float4 xv = *(const float4*)(Xt + k*xs + xoff);
        float4 wv = *(const float4*)(Wt + k*ws + wo);
        fma4(a0, xv.x, wv); fma4(a1, xv.y, wv);
        fma4(a2, xv.z, wv); fma4(a3, xv.w, wv);
    }
}
__device__ __forceinline__ void mm2_core(const float* __restrict__ Xt, int xs, int xoff,
                                         const float* __restrict__ Wt, int ws, int wo, int K,
                                         float4& a0, float4& a1)
{
    #pragma unroll 4
    for (int k = 0; k < K; k++) {
        float2 xv = *(const float2*)(Xt + k*xs + xoff);
        float4 wv = *(const float4*)(Wt + k*ws + wo);
        fma4(a0, xv.x, wv); fma4(a1, xv.y, wv);
    }
}
__device__ __forceinline__ void mm1_core(const float* __restrict__ X,
                                         const float* __restrict__ Wt, int ws, int wo, int K4,
                                         float4& a0)
{
    #pragma unroll 4
    for (int kk = 0; kk < K4; kk++) {
        float4 xk = ((const float4*)X)[kk];
        const float* base = Wt + kk*4*ws + wo;
        fma4(a0, xk.x, *(const float4*)(base));
        fma4(a0, xk.y, *(const float4*)(base + ws));
        fma4(a0, xk.z, *(const float4*)(base + 2*ws));
        fma4(a0, xk.w, *(const float4*)(base + 3*ws));
    }
}

// =====================================================================
// k_agg smem layout (floats)
// =====================================================================
#define OFF_WT0  0
#define OFF_WT1  10400
#define OFF_WT2  20800
#define OFF_WTL  31200
#define OFF_AT   41600   // [100][40] k-major level-2 input
#define OFF_BB   45600   // [36][100] row-major
#define OFF_G    49200   // [36][100] row-major raw E2
#define OFF_CT   52800   // [100][8]  k-major level-1 input
#define OFF_DD   53600   // [6][100]
#define OFF_E0A  54200
#define OFF_E0B  54300
#define OFF_IDS  54400   // ints 258
#define OFF_ITEM 54660
#define AGG_SM_FLOATS 54664
#define AGG_SM_BYTES  (AGG_SM_FLOATS*4)

__global__ __launch_bounds__(256, 1)
void k_agg(const int* __restrict__ question, const int* __restrict__ user,
           const int* __restrict__ mask,
           const int* __restrict__ q_nb, const int* __restrict__ s_nb,
           const int* __restrict__ u_nb, const int* __restrict__ q_nb2,
           const float* __restrict__ emb_q, const float* __restrict__ emb_q2,
           const float* __restrict__ emb_s, const float* __restrict__ emb_u,
           const float* __restrict__ agg_w, const float* __restrict__ agg_b,
           const float* __restrict__ W_al,  const float* __restrict__ b_al)
{
    extern __shared__ float sm[];
    float* At  = sm + OFF_AT;
    float* Bb  = sm + OFF_BB;
    float* G   = sm + OFF_G;
    float* Ct  = sm + OFF_CT;
    float* Dd  = sm + OFF_DD;
    float* E0A = sm + OFF_E0A;
    float* E0B = sm + OFF_E0B;
    int*   ids  = (int*)(sm + OFF_IDS);
    int*   ids2 = ids + 6;
    int*   ids3 = ids + 42;
    int*   s_item = ids + 258;
    int tid = threadIdx.x;

    const float* b0 = agg_b;
    const float* b1 = agg_b + 100;
    const float* b2 = agg_b + 200;

    // stage weights transposed: Wt[k*104+o] = W[o*100+k]
    for (int i = tid; i < 10000; i += 256) {
        int o = i / 100, k = i % 100;
        int s = k*104 + o;
        sm[OFF_WT0 + s] = agg_w[i];
        sm[OFF_WT1 + s] = agg_w[10000 + i];
        sm[OFF_WT2 + s] = agg_w[20000 + i];
        sm[OFF_WTL + s] = W_al[i];
    }

    float4* G4 = (float4*)G; float4* B4 = (float4*)Bb;
    float4* D4 = (float4*)Dd; float4* E0A4 = (float4*)E0A;

    for (;;) {
        __syncthreads();
        if (tid == 0) *s_item = atomicAdd(&g_ctr, 1);
        __syncthreads();
        int item = *s_item;
        if (item >= NITEM) break;
        int side = item & 1, pair = item >> 1;
        int b = pair / TS_, t = pair % TS_;
        int m  = mask[b*T_ + t];
        int qt = question[b*T_ + t];
        float* outp = (side == 0 ? g_e1 : g_e2) + pair * D_;

        if (!m) {
            if (tid < 25) {
                const float4* src = (const float4*)((side == 0 ? emb_q : emb_q2) + (size_t)qt*D_);
                ((float4*)outp)[tid] = src[tid];
            }
            continue;
        }

        int n0; const int *tabE, *tabO; const float *embE, *embO;
        if (side == 0) { n0 = qt;           tabE = q_nb; tabO = s_nb;  embE = emb_q; embO = emb_s;  }
        else           { n0 = user[b*T_+t]; tabE = u_nb; tabO = q_nb2; embE = emb_u; embO = emb_q2; }
        const float4* embE4 = (const float4*)embE;
        const float4* embO4 = (const float4*)embO;

        // P1: ids1 + E0
        if (tid < 6) ids[tid] = tabE[n0*6 + tid];
        if (tid >= 64 && tid < 89) E0A4[tid-64] = embE4[(size_t)n0*25 + (tid-64)];
        __syncthreads();
        // P2: ids2
        if (tid < 36) ids2[tid] = tabO[ids[tid/6]*6 + tid%6];
        __syncthreads();
        // P3: ids3, G(E2), Dd(E1)
        if (tid < 216) ids3[tid] = tabE[ids2[tid/6]*6 + tid%6];
        for (int i = tid; i < 900; i += 256)
            G4[i] = embE4[(size_t)ids2[i/25]*25 + i%25];
        if (tid < 150)
            D4[tid] = embO4[(size_t)ids[tid/25]*25 + tid%25];
        __syncthreads();
        // P4: Bb = mean6(E3)+G ; Ct = T(grpmean6(G)+Dd) ; E0A += mean6(Dd)
        for (int i = tid; i < 900; i += 256) {
            int j = i/25;
            float4 a = embO4[(size_t)ids3[j*6+0]*25 + i%25];
            #pragma unroll
            for (int r = 1; r < 6; r++) {
                float4 v = embO4[(size_t)ids3[j*6+r]*25 + i%25];
                a.x += v.x; a.y += v.y; a.z += v.z; a.w += v.w;
            }
            const float s6 = 1.f/6.f;
            float4 g = G4[i];
            a.x = a.x*s6 + g.x; a.y = a.y*s6 + g.y;
            a.z = a.z*s6 + g.z; a.w = a.w*s6 + g.w;
            B4[i] = a;
        }
        for (int i = tid; i < 600; i += 256) {
            int k = i % 100, r = i / 100;
            float s = 0.f;
            #pragma unroll
            for (int j = 0; j < 6; j++) s += G[(r*6+j)*100 + k];
            Ct[k*8 + r] = s * (1.f/6.f) + Dd[r*100 + k];
        }
        if (tid < 100) {
            float s = 0.f;
            #pragma unroll
            for (int r = 0; r < 6; r++) s += Dd[r*100 + tid];
            E0A[tid] += s * (1.f/6.f);
        }
        __syncthreads();
        // P5: At = T(Bb)
        for (int i = tid; i < 3600; i += 256) {
            int k = i % 100, j = i / 100;
            At[k*40 + j] = Bb[j*100 + k];
        }
        __syncthreads();
        // P6: pass0 mm (L2: At->Bb, L1: Ct->Dd, L0: E0A->E0B)
        for (int task = tid; task < 325; task += 256) {
            if (task < 225) {
                int rq = task / 25, cq = task % 25, wo = cq*4;
                float4 a0={0,0,0,0}, a1=a0, a2=a0, a3=a0;
                mm4_core(At, 40, rq*4, sm + OFF_WT2, 104, wo, 100, a0, a1, a2, a3);
                float4 bb = *(const float4*)(b2 + wo);
                *(float4*)(Bb + (rq*4+0)*100 + wo) = tanh4b(a0, bb);
                *(float4*)(Bb + (rq*4+1)*100 + wo) = tanh4b(a1, bb);
                *(float4*)(Bb + (rq*4+2)*100 + wo) = tanh4b(a2, bb);
                *(float4*)(Bb + (rq*4+3)*100 + wo) = tanh4b(a3, bb);
            } else if (task < 300) {
                int u = task - 225, rq = u / 25, cq = u % 25, wo = cq*4;
                float4 a0={0,0,0,0}, a1=a0;
                mm2_core(Ct, 8, rq*2, sm + OFF_WT1, 104, wo, 100, a0, a1);
                float4 bb = *(const float4*)(b1 + wo);
                *(float4*)(Dd + (rq*2+0)*100 + wo) = tanh4b(a0, bb);
                *(float4*)(Dd + (rq*2+1)*100 + wo) = tanh4b(a1, bb);
            } else {
                int cq = task - 300, wo = cq*4;
                float4 a0={0,0,0,0};
                mm1_core(E0A, sm + OFF_WT0, 104, wo, 25, a0);
                float4 bb = *(const float4*)(b0 + wo);
                *(float4*)(E0B + wo) = tanh4b(a0, bb);
            }
        }
        __syncthreads();
        // P7: Ct = T(grpmean6(Bb)+Dd) ; E0A = mean6(Dd)+E0B
        for (int i = tid; i < 600; i += 256) {
            int k = i % 100, r = i / 100;
            float s = 0.f;
            #pragma unroll
            for (int j = 0; j < 6; j++) s += Bb[(r*6+j)*100 + k];
            Ct[k*8 + r] = s * (1.f/6.f) + Dd[r*100 + k];
        }
        if (tid < 100) {
            float s = 0.f;
            #pragma unroll
            for (int r = 0; r < 6; r++) s += Dd[r*100 + tid];
            E0A[tid] = s * (1.f/6.f) + E0B[tid];
        }
        __syncthreads();
        // P8: pass1 mm (L1: Ct->Dd, L0: E0A->E0B)
        for (int task = tid; task < 100; task += 256) {
            if (task < 75) {
                int rq = task / 25, cq = task % 25, wo = cq*4;
                float4 a0={0,0,0,0}, a1=a0;
                mm2_core(Ct, 8, rq*2, sm + OFF_WT1, 104, wo, 100, a0, a1);
                float4 bb = *(const float4*)(b1 + wo);
                *(float4*)(Dd + (rq*2+0)*100 + wo) = tanh4b(a0, bb);
                *(float4*)(Dd + (rq*2+1)*100 + wo) = tanh4b(a1, bb);
            } else {
                int cq = task - 75, wo = cq*4;
                float4 a0={0,0,0,0};
                mm1_core(E0A, sm + OFF_WT0, 104, wo, 25, a0);
                float4 bb = *(const float4*)(b0 + wo);
                *(float4*)(E0B + wo) = tanh4b(a0, bb);
            }
        }
        __syncthreads();
        // P9: E0A = mean6(Dd)+E0B
        if (tid < 100) {
            float s = 0.f;
            #pragma unroll
            for (int r = 0; r < 6; r++) s += Dd[r*100 + tid];
            E0A[tid] = s * (1.f/6.f) + E0B[tid];
        }
        __syncthreads();
        // P10: pass2 (E0A->E0B)
        if (tid < 25) {
            int wo = tid*4;
            float4 a0={0,0,0,0};
            mm1_core(E0A, sm + OFF_WT0, 104, wo, 25, a0);
            float4 bb = *(const float4*)(b0 + wo);
            *(float4*)(E0B + wo) = tanh4b(a0, bb);
        }
        __syncthreads();
        // P11: final (E0B -> global)
        if (tid < 25) {
            int wo = tid*4;
            float4 a0={0,0,0,0};
            mm1_core(E0B, sm + OFF_WTL, 104, wo, 25, a0);
            float4 bb = *(const float4*)(b_al + wo);
            *(float4*)(outp + wo) = tanh4b(a0, bb);
        }
    }
}

// =====================================================================
// k_att: qs rows, ql -> (u, Zq), top-10
// =====================================================================
__device__ __forceinline__ unsigned long long att_key(float f, int j)
{
    unsigned bb = __float_as_uint(f);
    bb = (bb & 0x80000000u) ? ~bb : (bb | 0x80000000u);
    return ((unsigned long long)bb << 32) | (unsigned)(49 - j);
}

__global__ void k_att(const int* __restrict__ question, const int* __restrict__ qsi,
                      const float* __restrict__ emb_q, const float* __restrict__ emb_s)
{
    __shared__ float qs[5*D_];
    __shared__ float sc[T_];
    __shared__ float qlS[5];
    __shared__ float wqS[5];
    int t = blockIdx.x, b = blockIdx.y;
    int tid = threadIdx.x, lane = tid & 31, w = tid >> 5;
    int qn = question[b*T_ + t + 1];
    const float4* embq4 = (const float4*)emb_q;
    const float4* embs4 = (const float4*)emb_s;

    for (int i = tid; i < 125; i += 256) {
        int row = i/25, dq = i%25;
        float4 v = (row == 0) ? embq4[(size_t)qn*25 + dq]
                              : embs4[(size_t)qsi[qn*4 + row - 1]*25 + dq];
        ((float4*)qs)[i] = v;
    }
    __syncthreads();
    if (w < 5) {
        float s = 0.f;
        for (int d = lane; d < D_; d += 32) s += qs[w*D_ + d] * g_vq[d];
        for (int off = 16; off; off >>= 1) s += __shfl_down_sync(0xffffffffu, s, off);
        if (lane == 0) qlS[w] = s;
    }
    for (int j = w; j < T_; j += 8) {
        int qj = question[b*T_ + j];
        float s = 0.f;
        for (int d = lane; d < D_; d += 32) s += emb_q[(size_t)qj*D_ + d] * qs[d];
        for (int off = 16; off; off >>= 1) s += __shfl_down_sync(0xffffffffu, s, off);
        if (lane == 0) sc[j] = (j < t) ? s : NEGF;
    }
    __syncthreads();
    if (w == 0) {
        bool t1 = false, t2 = false;
        int j1 = lane, j2 = lane + 32;
        for (int i = 0; i < 10; i++) {
            unsigned long long k1 = (!t1) ? att_key(sc[j1], j1) : 0ull;
            unsigned long long k2 = (j2 < T_ && !t2) ? att_key(sc[j2], j2) : 0ull;
            unsigned long long mk = k1 > k2 ? k1 : k2;
            for (int off = 16; off; off >>= 1) {
                unsigned long long o = __shfl_xor_sync(0xffffffffu, mk, off);
                if (o > mk) mk = o;
            }
            int jwin = 49 - (int)(mk & 0xffffffffull);
            if (jwin == j1) t1 = true;
            if (jwin == j2) t2 = true;
            if (lane == 0) g_topk[(b*TS_ + t)*10 + i] = (jwin < t) ? jwin : -1;
        }
    }
    __syncthreads();
    if (tid == 0) {
        float mx = qlS[0];
        for (int i = 1; i < 5; i++) mx = fmaxf(mx, qlS[i]);
        float z = 0.f;
        for (int i = 0; i < 5; i++) { wqS[i] = __expf(qlS[i] - mx); z += wqS[i]; }
        g_zq[b*TS_ + t] = z;
    }
    __syncthreads();
    if (tid < D_) {
        float u = 0.f;
        #pragma unroll
        for (int j = 0; j < 5; j++) u += wqS[j] * qs[j*D_ + tid];
        g_u[(b*TS_ + t)*D_ + tid] = u;
    }
}

// =====================================================================
// k_fuse: 16 rows/block, grid 98.  Wt[200x104], Xt[200x20]
// =====================================================================
#define FUSE_WT 0
#define FUSE_X  20800
#define FUSE_XT 24000
#define FUSE_SM_FLOATS 28000
#define FUSE_SM_BYTES  (FUSE_SM_FLOATS*4)
__global__ __launch_bounds__(256, 1)
void k_fuse(const int* __restrict__ resp, const float* __restrict__ embr,
            const float* __restrict__ w1p, const float* __restrict__ w2p,
            const float* __restrict__ Wf, const float* __restrict__ bf)
{
    extern __shared__ float sm[];
    float* Wt = sm + FUSE_WT;
    float* X  = sm + FUSE_X;
    float* Xt = sm + FUSE_XT;
    int tid = threadIdx.x, g0 = blockIdx.x * 16;
    float w1 = *w1p, w2 = *w2p;
    for (int i = tid; i < 20000; i += 256) {
        int o = i / 200, k = i % 200;
        Wt[k*104 + o] = Wf[i];
    }
    for (int i = tid; i < 3200; i += 256) {
        int r = i / 200, k = i % 200;
        int g = g0 + r, b = g / TS_, t = g % TS_;
        X[i] = (k < D_)
             ? (w1 * g_e1[g*D_ + k] + w2 * g_e2[g*D_ + k])
             : embr[resp[b*T_ + t]*D_ + (k - D_)];
    }
    __syncthreads();
    for (int i = tid; i < 3200; i += 256) {
        int k = i % 200, r = i / 200;
        Xt[k*20 + r] = X[r*200 + k];
    }
    __syncthreads();
    // RT4 x CT2 -> 200 tasks
    for (int task = tid; task < 200; task += 256) {
        int rq = task / 50, c2 = task % 50, wo = c2*2;
        float2 a0={0,0}, a1=a0, a2=a0, a3=a0;
        #pragma unroll 4
        for (int k = 0; k < 200; k++) {
            float4 xv = *(const float4*)(Xt + k*20 + rq*4);
            float2 wv = *(const float2*)(Wt + k*104 + wo);
            a0.x += xv.x*wv.x; a0.y += xv.x*wv.y;
            a1.x += xv.y*wv.x; a1.y += xv.y*wv.y;
            a2.x += xv.z*wv.x; a2.y += xv.z*wv.y;
            a3.x += xv.w*wv.x; a3.y += xv.w*wv.y;
        }
        float2 bb = *(const float2*)(bf + wo);
        int r0 = g0 + rq*4;
        float2 o0 = {fmaxf(a0.x+bb.x,0.f), fmaxf(a0.y+bb.y,0.f)};
        float2 o1 = {fmaxf(a1.x+bb.x,0.f), fmaxf(a1.y+bb.y,0.f)};
        float2 o2 = {fmaxf(a2.x+bb.x,0.f), fmaxf(a2.y+bb.y,0.f)};
        float2 o3 = {fmaxf(a3.x+bb.x,0.f), fmaxf(a3.y+bb.y,0.f)};
        *(float2*)(g_et + (r0+0)*D_ + wo) = o0;
        *(float2*)(g_et + (r0+1)*D_ + wo) = o1;
        *(float2*)(g_et + (r0+2)*D_ + wo) = o2;
        *(float2*)(g_et + (r0+3)*D_ + wo) = o3;
    }
}

// =====================================================================
// k_ih: 16 rows/block, grid 98.  Wt[100x404], Xt[100x20]
// =====================================================================
#define IH_WT 0
#define IH_X  40400
#define IH_XT 42000
#define IH_SM_FLOATS 44000
#define IH_SM_BYTES  (IH_SM_FLOATS*4)
__global__ __launch_bounds__(256, 1)
void k_ih(const float* __restrict__ Wih, const float* __restrict__ bih,
          const float* __restrict__ bhh)
{
    extern __shared__ float sm[];
    float* Wt = sm + IH_WT;
    float* X  = sm + IH_X;
    float* Xt = sm + IH_XT;
    int tid = threadIdx.x, g0 = blockIdx.x * 16;
    for (int i = tid; i < 40000; i += 256) {
        int o = i / 100, k = i % 100;
        Wt[k*404 + o] = Wih[i];
    }
    for (int i = tid; i < 1600; i += 256) X[i] = g_et[g0*D_ + i];
    __syncthreads();
    for (int i = tid; i < 1600; i += 256) {
        int k = i % 100, r = i / 100;
        Xt[k*20 + r] = X[r*100 + k];
    }
    __syncthreads();
    // RT4 x CT4 over 400 cols -> 400 tasks
    for (int task = tid; task < 400; task += 256) {
        int rq = task / 100, cq = task % 100, wo = cq*4;
        float4 a0={0,0,0,0}, a1=a0, a2=a0, a3=a0;
        mm4_core(Xt, 20, rq*4, Wt, 404, wo, 100, a0, a1, a2, a3);
        float4 bi = *(const float4*)(bih + wo);
        float4 bh = *(const float4*)(bhh + wo);
        float4 bb = {bi.x+bh.x, bi.y+bh.y, bi.z+bh.z, bi.w+bh.w};
        int r0 = g0 + rq*4;
        float4 o0 = {a0.x+bb.x, a0.y+bb.y, a0.z+bb.z, a0.w+bb.w};
        float4 o1 = {a1.x+bb.x, a1.y+bb.y, a1.z+bb.z, a1.w+bb.w};
        float4 o2 = {a2.x+bb.x, a2.y+bb.y, a2.z+bb.z, a2.w+bb.w};
        float4 o3 = {a3.x+bb.x, a3.y+bb.y, a3.z+bb.z, a3.w+bb.w};
        *(float4*)(g_preg + (r0+0)*400 + wo) = o0;
        *(float4*)(g_preg + (r0+1)*400 + wo) = o1;
        *(float4*)(g_preg + (r0+2)*400 + wo) = o2;
        *(float4*)(g_preg + (r0+3)*400 + wo) = o3;
    }
}

// =====================================================================
// k_lstm: per-batch recurrence only. 2 barriers/step.
// =====================================================================
__global__ __launch_bounds__(800, 1)
void k_lstm(const int* __restrict__ mask, const float* __restrict__ Whh,
            float* __restrict__ out)
{
    __shared__ float h[104];
    __shared__ float pp[800];
    __shared__ int maskS[T_];

    int b = blockIdx.x, tid = threadIdx.x;
    int o = tid >> 1, half = tid & 1;

    float4 w[13];
    {
        const float4* Wr = (const float4*)(Whh + o*D_ + half*52);
        #pragma unroll
        for (int j = 0; j < 13; j++)
            if (half == 0 || j < 12) w[j] = __ldg(Wr + j);
    }
    float creg = 0.f;
    if (tid < D_) h[tid] = 0.f;
    if (tid < T_) maskS[tid] = mask[b*T_ + tid];
    if (tid == 0) out[b*T_] = 0.5f;
    __syncthreads();

    for (int t = 0; t < TS_; t++) {
        const float* G0 = g_preg + (size_t)(b*TS_ + t) * 400;
        // prefetch G0 gates for this thread's dim (threads < 100)
        float gI=0.f, gF=0.f, gG=0.f, gO=0.f;
        if (tid < D_) {
            gI = __ldg(G0 + tid);        gF = __ldg(G0 + D_ + tid);
            gG = __ldg(G0 + 2*D_ + tid); gO = __ldg(G0 + 3*D_ + tid);
        }
        // partial GEMV
        {
            float acc = 0.f;
            const float4* h4 = (const float4*)h;
            if (half == 0) {
                #pragma unroll
                for (int j = 0; j < 13; j++) {
                    float4 hv = h4[j];
                    acc += w[j].x*hv.x + w[j].y*hv.y + w[j].z*hv.z + w[j].w*hv.w;
                }
            } else {
                #pragma unroll
                for (int j = 0; j < 12; j++) {
                    float4 hv = h4[13 + j];
                    acc += w[j].x*hv.x + w[j].y*hv.y + w[j].z*hv.z + w[j].w*hv.w;
                }
            }
            pp[tid] = acc;
        }
        __syncthreads();
        if (tid < D_) {
            int d2 = tid*2;
            float ai = gI + pp[d2]       + pp[d2+1];
            float af = gF + pp[200 + d2] + pp[200 + d2+1];
            float ag = gG + pp[400 + d2] + pp[400 + d2+1];
            float ao = gO + pp[600 + d2] + pp[600 + d2+1];
            float c2 = fast_sig(af) * creg + fast_sig(ai) * fast_tanh(ag);
            float h2 = fast_sig(ao) * fast_tanh(c2);
            if (maskS[t]) { creg = c2; h[tid] = h2; }
            g_sh[(size_t)(b*TS_ + t)*D_ + tid] = h[tid];
        }
        __syncthreads();
    }
}

// =====================================================================
// k_attn: fully parallel over (b,t). 128 threads/block.
// =====================================================================
__global__ __launch_bounds__(128)
void k_attn(float* __restrict__ out)
{
    __shared__ float uS[D_], vkS[D_];
    __shared__ float kls[12], dots[12];
    __shared__ int idxS[10];
    int t = blockIdx.x, b = blockIdx.y;
    int tid = threadIdx.x, lane = tid & 31, w = tid >> 5;
    int row0 = b*TS_ + t;

    if (tid < D_) { uS[tid] = g_u[(size_t)row0*D_ + tid]; vkS[tid] = g_vk[tid]; }
    if (tid >= 100 && tid < 110) idxS[tid-100] = g_topk[row0*10 + (tid-100)];
    __syncthreads();

    for (int j = w; j < 11; j += 4) {
        int rr = (j == 0) ? t : idxS[j-1];
        float s1 = 0.f, s2 = 0.f;
        if (rr >= 0) {
            const float* hp = g_sh + (size_t)(b*TS_ + rr)*D_;
            for (int d = lane; d < D_; d += 32) {
                float hv = hp[d];
                s1 += hv * vkS[d];
                s2 += hv * uS[d];
            }
        }
        for (int off = 16; off; off >>= 1) {
            s1 += __shfl_down_sync(0xffffffffu, s1, off);
            s2 += __shfl_down_sync(0xffffffffu, s2, off);
        }
        if (lane == 0) {
            kls[j]  = (rr >= 0) ? s1 : NEGF;
            dots[j] = (rr >= 0) ? s2 : 0.f;
        }
    }
    __syncthreads();
    if (w == 0) {
        float k = (lane < 11) ? kls[lane] : NEGF;
        float d = (lane < 11) ? dots[lane] : 0.f;
        float m = k;
        for (int off = 16; off; off >>= 1) m = fmaxf(m, __shfl_xor_sync(0xffffffffu, m, off));
        float e = (lane < 11) ? __expf(k - m) : 0.f;
        float num = e * d;
        float z = e;
        for (int off = 16; off; off >>= 1) {
            z   += __shfl_xor_sync(0xffffffffu, z, off);
            num += __shfl_xor_sync(0xffffffffu, num, off);
        }
        if (lane == 0) {
            float y = num / (g_zq[row0] * z);
            out[b*T_ + t + 1] = fast_sig(y);
        }
    }
}

// =====================================================================
// launch
// =====================================================================
extern "C" void kernel_launch(void* const* d_in, const int* in_sizes, int n_in,
                              void* d_out, int out_size)
{
    const int*   user      = (const int*)  d_in[0];
    const int*   question  = (const int*)  d_in[1];
    const int*   response  = (const int*)  d_in[2];
    const int*   mask      = (const int*)  d_in[3];
    const int*   q_nb      = (const int*)  d_in[4];
    const int*   s_nb      = (const int*)  d_in[5];
    const int*   u_nb      = (const int*)  d_in[6];
    const int*   q_nb2     = (const int*)  d_in[7];
    const int*   qsi       = (const int*)  d_in[8];
    const float* emb_q     = (const float*)d_in[9];
    const float* emb_q2    = (const float*)d_in[10];
    const float* emb_s     = (const float*)d_in[11];
    const float* emb_u     = (const float*)d_in[12];
    const float* emb_r     = (const float*)d_in[13];
    const float* w1p       = (const float*)d_in[14];
    const float* w2p       = (const float*)d_in[15];
    const float* W_ih      = (const float*)d_in[16];
    const float* W_hh      = (const float*)d_in[17];
    const float* b_ih      = (const float*)d_in[18];
    const float* b_hh      = (const float*)d_in[19];
    const float* agg_w     = (const float*)d_in[20];
    const float* agg_b     = (const float*)d_in[21];
    const float* W_al      = (const float*)d_in[22];
    const float* b_al      = (const float*)d_in[23];
    const float* W_q       = (const float*)d_in[24];
    const float* W_k       = (const float*)d_in[26];
    const float* W_w       = (const float*)d_in[28];
    const float* W_f       = (const float*)d_in[30];
    const float* b_f       = (const float*)d_in[31];
    float* out = (float*)d_out;
    (void)in_sizes; (void)n_in; (void)out_size;

    cudaFuncSetAttribute(k_agg,  cudaFuncAttributeMaxDynamicSharedMemorySize, AGG_SM_BYTES);
    cudaFuncSetAttribute(k_fuse, cudaFuncAttributeMaxDynamicSharedMemorySize, FUSE_SM_BYTES);
    cudaFuncSetAttribute(k_ih,   cudaFuncAttributeMaxDynamicSharedMemorySize, IH_SM_BYTES);

    k_prep<<<1, 128>>>(W_q, W_k, W_w);
    k_agg<<<148, 256, AGG_SM_BYTES>>>(question, user, mask,
        q_nb, s_nb, u_nb, q_nb2, emb_q, emb_q2, emb_s, emb_u,
        agg_w, agg_b, W_al, b_al);
    k_att<<<dim3(TS_, B_), 256>>>(question, qsi, emb_q, emb_s);
    k_fuse<<<98, 256, FUSE_SM_BYTES>>>(response, emb_r, w1p, w2p, W_f, b_f);
    k_ih<<<98, 256, IH_SM_BYTES>>>(W_ih, b_ih, b_hh);
    k_lstm<<<B_, 800>>>(mask, W_hh, out);
    k_attn<<<dim3(TS_, B_), 128>>>(out);
}

// round 10
// speedup vs baseline: 2.1038x; 1.1913x over previous
#include <cuda_runtime.h>
#include <cuda_bf16.h>
#include <math.h>

#define B_   32
#define T_   50
#define TS_  49
#define D_   100
#define NEGF (-1000000000.0f)
#define NROW (B_*TS_)   // 1568
#define NITEM (NROW*2)  // 3136

typedef unsigned long long u64;

// ---------------- device scratch ----------------
__device__ float g_e1[NROW*D_];
__device__ float g_e2[NROW*D_];
__device__ float g_et[NROW*D_];
__device__ float g_preg[NROW*400];
__device__ float g_u[NROW*D_];
__device__ float g_zq[NROW];
__device__ int   g_topk[NROW*10];
__device__ float g_vq[D_];
__device__ float g_vk[D_];
__device__ int   g_ctr;

// ---------------- fast activations ----------------
__device__ __forceinline__ float fast_sig(float x)  { return __fdividef(1.f, 1.f + __expf(-x)); }
__device__ __forceinline__ float fast_tanh(float x) { return 1.f - __fdividef(2.f, __expf(2.f*x) + 1.f); }

// ---------------- f32x2 packed-FMA helpers ----------------
__device__ __forceinline__ u64 pk(float x) {
    u64 r; asm("mov.b64 %0, {%1,%1};" : "=l"(r) : "f"(x)); return r;
}
__device__ __forceinline__ void fmx(u64& a, u64 x, u64 w) {
    asm("fma.rn.f32x2 %0, %1, %2, %0;" : "+l"(a) : "l"(x), "l"(w));
}
__device__ __forceinline__ float2 upk(u64 a) {
    float2 f; asm("mov.b64 {%0,%1}, %2;" : "=f"(f.x), "=f"(f.y) : "l"(a)); return f;
}
__device__ __forceinline__ void fma4(float4& a, float x, const float4& w) {
    a.x += x*w.x; a.y += x*w.y; a.z += x*w.z; a.w += x*w.w;
}

// =====================================================================
// k_prep
// =====================================================================
__global__ void k_prep(const float* __restrict__ Wq, const float* __restrict__ Wk,
                       const float* __restrict__ Ww)
{
    int d = threadIdx.x;
    if (d < D_) {
        float a = 0.f, c = 0.f;
        for (int e = 0; e < D_; e++) {
            a += Ww[e]       * Wq[e*D_ + d];
            c += Ww[D_ + e]  * Wk[e*D_ + d];
        }
        g_vq[d] = a; g_vk[d] = c;
    }
    if (d == 112) g_ctr = 0;
}

// =====================================================================
// mm cores. X k-major, W k-major (stride ws).
// =====================================================================
// 4 rows x 4 cols, f32x2
__device__ __forceinline__ void mm4_x2(const float* __restrict__ Xt, int xs, int xoff,
                                       const float* __restrict__ Wt, int ws, int wo, int K,
                                       u64* a) // a[8]: row r -> a[2r], a[2r+1]
{
    #pragma unroll 2
    for (int k = 0; k < K; k++) {
        float4 xv = *(const float4*)(Xt + k*xs + xoff);
        ulonglong2 wv = *(const ulonglong2*)(Wt + k*ws + wo);
        u64 p0 = pk(xv.x), p1 = pk(xv.y), p2 = pk(xv.z), p3 = pk(xv.w);
        fmx(a[0], p0, wv.x); fmx(a[1], p0, wv.y);
        fmx(a[2], p1, wv.x); fmx(a[3], p1, wv.y);
        fmx(a[4], p2, wv.x); fmx(a[5], p2, wv.y);
        fmx(a[6], p3, wv.x); fmx(a[7], p3, wv.y);
    }
}
// 2 rows x 4 cols, f32x2
__device__ __forceinline__ void mm2_x2(const float* __restrict__ Xt, int xs, int xoff,
                                       const float* __restrict__ Wt, int ws, int wo, int K,
                                       u64* a) // a[4]
{
    #pragma unroll 2
    for (int k = 0; k < K; k++) {
        float2 xv = *(const float2*)(Xt + k*xs + xoff);
        ulonglong2 wv = *(const ulonglong2*)(Wt + k*ws + wo);
        u64 p0 = pk(xv.x), p1 = pk(xv.y);
        fmx(a[0], p0, wv.x); fmx(a[1], p0, wv.y);
        fmx(a[2], p1, wv.x); fmx(a[3], p1, wv.y);
    }
}
// 1 row x 4 cols, scalar (X row-major contiguous)
__device__ __forceinline__ void mm1_core(const float* __restrict__ X,
                                         const float* __restrict__ Wt, int ws, int wo, int K4,
                                         float4& a0)
{
    #pragma unroll 4
    for (int kk = 0; kk < K4; kk++) {
        float4 xk = ((const float4*)X)[kk];
        const float* base = Wt + kk*4*ws + wo;
        fma4(a0, xk.x, *(const float4*)(base));
        fma4(a0, xk.y, *(const float4*)(base + ws));
        fma4(a0, xk.z, *(const float4*)(base + 2*ws));
        fma4(a0, xk.w, *(const float4*)(base + 3*ws));
    }
}

__device__ __forceinline__ float4 tanh_2x2(u64 a01, u64 a23, float4 bb) {
    float2 lo = upk(a01), hi = upk(a23);
    float4 r;
    r.x = fast_tanh(lo.x + bb.x); r.y = fast_tanh(lo.y + bb.y);
    r.z = fast_tanh(hi.x + bb.z); r.w = fast_tanh(hi.y + bb.w);
    return r;
}

// =====================================================================
// k_agg: 512 threads = two independent 256-thread halves, each pulling
// items off the atomic queue. Weights (W0,W1,W2) shared k-major in smem.
// =====================================================================
#define HALF_FLOATS 9600
#define AGG_SM_FLOATS (31200 + 2*HALF_FLOATS)   // 50400 floats = 201.6 KB
#define AGG_SM_BYTES  (AGG_SM_FLOATS*4)

__global__ __launch_bounds__(512, 1)
void k_agg(const int* __restrict__ question, const int* __restrict__ user,
           const int* __restrict__ mask,
           const int* __restrict__ q_nb, const int* __restrict__ s_nb,
           const int* __restrict__ u_nb, const int* __restrict__ q_nb2,
           const float* __restrict__ emb_q, const float* __restrict__ emb_q2,
           const float* __restrict__ emb_s, const float* __restrict__ emb_u,
           const float* __restrict__ agg_w, const float* __restrict__ agg_b,
           const float* __restrict__ W_al,  const float* __restrict__ b_al)
{
    extern __shared__ float sm[];
    int tid = threadIdx.x;
    int hf  = tid >> 8;          // 0 or 1
    int htid = tid & 255;

    // shared weights, k-major: WT[k*104 + o]
    float* WT0 = sm;
    float* WT1 = sm + 10400;
    float* WT2 = sm + 20800;
    for (int i = tid; i < 10000; i += 512) {
        int o = i / 100, k = i % 100;
        int s = k*104 + o;
        WT0[s] = agg_w[i];
        WT1[s] = agg_w[10000 + i];
        WT2[s] = agg_w[20000 + i];
    }

    // per-half buffers
    float* HB  = sm + 31200 + hf*HALF_FLOATS;
    float* At  = HB;            // [100][40] (transpose buf); first 3600 = raw E2 (G)
    float* G   = HB;            // alias (G dead before At written)
    float* Bb  = HB + 4000;     // [36][100]
    float* Ct  = HB + 7600;     // [100][8]
    float* Dd  = HB + 8400;     // [6][100]
    float* E0A = HB + 9000;     // 104
    float* E0B = HB + 9104;     // 104
    int*   ids  = (int*)(HB + 9208);
    int*   ids2 = ids + 6;
    int*   ids3 = ids + 42;
    int*   s_item = ids + 258;

    const float* b0 = agg_b;
    const float* b1 = agg_b + 100;
    const float* b2 = agg_b + 200;

    float4* G4 = (float4*)G; float4* D4 = (float4*)Dd; float4* E0A4 = (float4*)E0A;

    __syncthreads();

    #define HBAR() asm volatile("bar.sync %0, 256;" :: "r"(hf+1) : "memory")

    for (;;) {
        HBAR();
        if (htid == 0) *s_item = atomicAdd(&g_ctr, 1);
        HBAR();
        int item = *s_item;
        if (item >= NITEM) break;
        int side = item & 1, pair = item >> 1;
        int b = pair / TS_, t = pair % TS_;
        int m  = mask[b*T_ + t];
        int qt = question[b*T_ + t];
        float* outp = (side == 0 ? g_e1 : g_e2) + pair * D_;

        if (!m) {
            if (htid < 25) {
                const float4* src = (const float4*)((side == 0 ? emb_q : emb_q2) + (size_t)qt*D_);
                ((float4*)outp)[htid] = src[htid];
            }
            continue;
        }

        int n0; const int *tabE, *tabO; const float *embE, *embO;
        if (side == 0) { n0 = qt;           tabE = q_nb; tabO = s_nb;  embE = emb_q; embO = emb_s;  }
        else           { n0 = user[b*T_+t]; tabE = u_nb; tabO = q_nb2; embE = emb_u; embO = emb_q2; }
        const float4* embE4 = (const float4*)embE;
        const float4* embO4 = (const float4*)embO;

        // P1: ids1 + E0
        if (htid < 6) ids[htid] = tabE[n0*6 + htid];
        if (htid >= 64 && htid < 89) E0A4[htid-64] = embE4[(size_t)n0*25 + (htid-64)];
        HBAR();
        // P2: ids2
        if (htid < 36) ids2[htid] = tabO[ids[htid/6]*6 + htid%6];
        HBAR();
        // P3: ids3, G (raw E2), Dd (E1)
        if (htid < 216) ids3[htid] = tabE[ids2[htid/6]*6 + htid%6];
        for (int i = htid; i < 900; i += 256)
            G4[i] = embE4[(size_t)ids2[i/25]*25 + i%25];
        if (htid < 150)
            D4[htid] = embO4[(size_t)ids[htid/25]*25 + htid%25];
        HBAR();
        // P4: Bb = mean6(E3)+G ; Ct = T(grpmean6(G)+E1) ; E0A += mean6(E1)
        for (int i = htid; i < 900; i += 256) {
            int j = i/25;
            float4 a = embO4[(size_t)ids3[j*6+0]*25 + i%25];
            #pragma unroll
            for (int r = 1; r < 6; r++) {
                float4 v = embO4[(size_t)ids3[j*6+r]*25 + i%25];
                a.x += v.x; a.y += v.y; a.z += v.z; a.w += v.w;
            }
            const float s6 = 1.f/6.f;
            float4 g = G4[i];
            a.x = a.x*s6 + g.x; a.y = a.y*s6 + g.y;
            a.z = a.z*s6 + g.z; a.w = a.w*s6 + g.w;
            ((float4*)Bb)[i] = a;
        }
        for (int i = htid; i < 600; i += 256) {
            int k = i % 100, r = i / 100;
            float s = 0.f;
            #pragma unroll
            for (int j = 0; j < 6; j++) s += G[(r*6+j)*100 + k];
            Ct[k*8 + r] = s * (1.f/6.f) + Dd[r*100 + k];
        }
        if (htid < 100) {
            float s = 0.f;
            #pragma unroll
            for (int r = 0; r < 6; r++) s += Dd[r*100 + htid];
            E0A[htid] += s * (1.f/6.f);
        }
        HBAR();
        // P5: At = T(Bb)   (G buffer dead -> At overlays it)
        for (int i = htid; i < 3600; i += 256) {
            int j = i % 36, k = i / 36;
            At[k*40 + j] = Bb[j*100 + k];
        }
        HBAR();
        // P6: pass0 mm (L2: At->Bb, L1: Ct->Dd, L0: E0A->E0B)
        for (int task = htid; task < 325; task += 256) {
            if (task < 225) {
                int rq = task / 25, cq = task % 25, wo = cq*4;
                u64 a[8] = {0,0,0,0,0,0,0,0};
                mm4_x2(At, 40, rq*4, WT2, 104, wo, 100, a);
                float4 bb = *(const float4*)(b2 + wo);
                *(float4*)(Bb + (rq*4+0)*100 + wo) = tanh_2x2(a[0], a[1], bb);
                *(float4*)(Bb + (rq*4+1)*100 + wo) = tanh_2x2(a[2], a[3], bb);
                *(float4*)(Bb + (rq*4+2)*100 + wo) = tanh_2x2(a[4], a[5], bb);
                *(float4*)(Bb + (rq*4+3)*100 + wo) = tanh_2x2(a[6], a[7], bb);
            } else if (task < 300) {
                int u = task - 225, rq = u / 25, cq = u % 25, wo = cq*4;
                u64 a[4] = {0,0,0,0};
                mm2_x2(Ct, 8, rq*2, WT1, 104, wo, 100, a);
                float4 bb = *(const float4*)(b1 + wo);
                *(float4*)(Dd + (rq*2+0)*100 + wo) = tanh_2x2(a[0], a[1], bb);
                *(float4*)(Dd + (rq*2+1)*100 + wo) = tanh_2x2(a[2], a[3], bb);
            } else {
                int cq = task - 300, wo = cq*4;
                float4 a0 = {0,0,0,0};
                mm1_core(E0A, WT0, 104, wo, 25, a0);
                float4 bb = *(const float4*)(b0 + wo);
                float4 o = {fast_tanh(a0.x+bb.x), fast_tanh(a0.y+bb.y),
                            fast_tanh(a0.z+bb.z), fast_tanh(a0.w+bb.w)};
                *(float4*)(E0B + wo) = o;
            }
        }
        HBAR();
        // P7: Ct = T(grpmean6(Bb)+Dd) ; E0A = mean6(Dd)+E0B
        for (int i = htid; i < 600; i += 256) {
            int k = i % 100, r = i / 100;
            float s = 0.f;
            #pragma unroll
            for (int j = 0; j < 6; j++) s += Bb[(r*6+j)*100 + k];
            Ct[k*8 + r] = s * (1.f/6.f) + Dd[r*100 + k];
        }
        if (htid < 100) {
            float s = 0.f;
            #pragma unroll
            for (int r = 0; r < 6; r++) s += Dd[r*100 + htid];
            E0A[htid] = s * (1.f/6.f) + E0B[htid];
        }
        HBAR();
        // P8: pass1 mm
        for (int task = htid; task < 100; task += 256) {
            if (task < 75) {
                int rq = task / 25, cq = task % 25, wo = cq*4;
                u64 a[4] = {0,0,0,0};
                mm2_x2(Ct, 8, rq*2, WT1, 104, wo, 100, a);
                float4 bb = *(const float4*)(b1 + wo);
                *(float4*)(Dd + (rq*2+0)*100 + wo) = tanh_2x2(a[0], a[1], bb);
                *(float4*)(Dd + (rq*2+1)*100 + wo) = tanh_2x2(a[2], a[3], bb);
            } else {
                int cq = task - 75, wo = cq*4;
                float4 a0 = {0,0,0,0};
                mm1_core(E0A, WT0, 104, wo, 25, a0);
                float4 bb = *(const float4*)(b0 + wo);
                float4 o = {fast_tanh(a0.x+bb.x), fast_tanh(a0.y+bb.y),
                            fast_tanh(a0.z+bb.z), fast_tanh(a0.w+bb.w)};
                *(float4*)(E0B + wo) = o;
            }
        }
        HBAR();
        // P9: E0A = mean6(Dd)+E0B
        if (htid < 100) {
            float s = 0.f;
            #pragma unroll
            for (int r = 0; r < 6; r++) s += Dd[r*100 + htid];
            E0A[htid] = s * (1.f/6.f) + E0B[htid];
        }
        HBAR();
        // P10: E0B = tanh(W0^T E0A + b0)
        if (htid < 25) {
            int wo = htid*4;
            float4 a0 = {0,0,0,0};
            mm1_core(E0A, WT0, 104, wo, 25, a0);
            float4 bb = *(const float4*)(b0 + wo);
            float4 o = {fast_tanh(a0.x+bb.x), fast_tanh(a0.y+bb.y),
                        fast_tanh(a0.z+bb.z), fast_tanh(a0.w+bb.w)};
            *(float4*)(E0B + wo) = o;
        }
        HBAR();
        // P11: out = tanh(WL E0B + bl) — WL rows direct from L2, one row/thread
        if (htid < 100) {
            const float4* wl4 = (const float4*)(W_al + htid*100);
            const float4* e4  = (const float4*)E0B;
            float acc = 0.f;
            #pragma unroll 5
            for (int j = 0; j < 25; j++) {
                float4 w = __ldg(wl4 + j);
                float4 e = e4[j];
                acc += w.x*e.x + w.y*e.y + w.z*e.z + w.w*e.w;
            }
            outp[htid] = fast_tanh(acc + __ldg(b_al + htid));
        }
    }
    #undef HBAR
}

// =====================================================================
// k_att: qs rows, ql -> (u, Zq), top-10
// =====================================================================
__device__ __forceinline__ unsigned long long att_key(float f, int j)
{
    unsigned bb = __float_as_uint(f);
    bb = (bb & 0x80000000u) ? ~bb : (bb | 0x80000000u);
    return ((unsigned long long)bb << 32) | (unsigned)(49 - j);
}

__global__ void k_att(const int* __restrict__ question, const int* __restrict__ qsi,
                      const float* __restrict__ emb_q, const float* __restrict__ emb_s)
{
    __shared__ float qs[5*D_];
    __shared__ float sc[T_];
    __shared__ float qlS[5];
    __shared__ float wqS[5];
    int t = blockIdx.x, b = blockIdx.y;
    int tid = threadIdx.x, lane = tid & 31, w = tid >> 5;
    int qn = question[b*T_ + t + 1];
    const float4* embq4 = (const float4*)emb_q;
    const float4* embs4 = (const float4*)emb_s;

    for (int i = tid; i < 125; i += 256) {
        int row = i/25, dq = i%25;
        float4 v = (row == 0) ? embq4[(size_t)qn*25 + dq]
                              : embs4[(size_t)qsi[qn*4 + row - 1]*25 + dq];
        ((float4*)qs)[i] = v;
    }
    __syncthreads();
    if (w < 5) {
        float s = 0.f;
        for (int d = lane; d < D_; d += 32) s += qs[w*D_ + d] * g_vq[d];
        for (int off = 16; off; off >>= 1) s += __shfl_down_sync(0xffffffffu, s, off);
        if (lane == 0) qlS[w] = s;
    }
    for (int j = w; j < T_; j += 8) {
        int qj = question[b*T_ + j];
        float s = 0.f;
        for (int d = lane; d < D_; d += 32) s += emb_q[(size_t)qj*D_ + d] * qs[d];
        for (int off = 16; off; off >>= 1) s += __shfl_down_sync(0xffffffffu, s, off);
        if (lane == 0) sc[j] = (j < t) ? s : NEGF;
    }
    __syncthreads();
    if (w == 0) {
        bool t1 = false, t2 = false;
        int j1 = lane, j2 = lane + 32;
        for (int i = 0; i < 10; i++) {
            unsigned long long k1 = (!t1) ? att_key(sc[j1], j1) : 0ull;
            unsigned long long k2 = (j2 < T_ && !t2) ? att_key(sc[j2], j2) : 0ull;
            unsigned long long mk = k1 > k2 ? k1 : k2;
            for (int off = 16; off; off >>= 1) {
                unsigned long long o = __shfl_xor_sync(0xffffffffu, mk, off);
                if (o > mk) mk = o;
            }
            int jwin = 49 - (int)(mk & 0xffffffffull);
            if (jwin == j1) t1 = true;
            if (jwin == j2) t2 = true;
            if (lane == 0) g_topk[(b*TS_ + t)*10 + i] = (jwin < t) ? jwin : -1;
        }
    }
    __syncthreads();
    if (tid == 0) {
        float mx = qlS[0];
        for (int i = 1; i < 5; i++) mx = fmaxf(mx, qlS[i]);
        float z = 0.f;
        for (int i = 0; i < 5; i++) { wqS[i] = __expf(qlS[i] - mx); z += wqS[i]; }
        g_zq[b*TS_ + t] = z;
    }
    __syncthreads();
    if (tid < D_) {
        float u = 0.f;
        #pragma unroll
        for (int j = 0; j < 5; j++) u += wqS[j] * qs[j*D_ + tid];
        g_u[(b*TS_ + t)*D_ + tid] = u;
    }
}

// =====================================================================
// k_fuse: 16 rows/block, grid 98. Wt[200x104] k-major, Xt[200x20]
// =====================================================================
#define FUSE_WT 0
#define FUSE_X  20800
#define FUSE_XT 24000
#define FUSE_SM_FLOATS 28000
#define FUSE_SM_BYTES  (FUSE_SM_FLOATS*4)
__global__ __launch_bounds__(256, 1)
void k_fuse(const int* __restrict__ resp, const float* __restrict__ embr,
            const float* __restrict__ w1p, const float* __restrict__ w2p,
            const float* __restrict__ Wf, const float* __restrict__ bf)
{
    extern __shared__ float sm[];
    float* Wt = sm + FUSE_WT;
    float* X  = sm + FUSE_X;
    float* Xt = sm + FUSE_XT;
    int tid = threadIdx.x, g0 = blockIdx.x * 16;
    float w1 = *w1p, w2 = *w2p;
    for (int i = tid; i < 20000; i += 256) {
        int o = i / 200, k = i % 200;
        Wt[k*104 + o] = Wf[i];
    }
    for (int i = tid; i < 3200; i += 256) {
        int r = i / 200, k = i % 200;
        int g = g0 + r, b = g / TS_, t = g % TS_;
        X[i] = (k < D_)
             ? (w1 * g_e1[g*D_ + k] + w2 * g_e2[g*D_ + k])
             : embr[resp[b*T_ + t]*D_ + (k - D_)];
    }
    __syncthreads();
    for (int i = tid; i < 3200; i += 256) {
        int k = i % 200, r = i / 200;
        Xt[k*20 + r] = X[r*200 + k];
    }
    __syncthreads();
    // RT2 x CT4 -> 200 tasks
    for (int task = tid; task < 200; task += 256) {
        int rg = task / 25, cq = task % 25, wo = cq*4;
        u64 a[4] = {0,0,0,0};
        mm2_x2(Xt, 20, rg*2, Wt, 104, wo, 200, a);
        float4 bb = *(const float4*)(bf + wo);
        float2 l0 = upk(a[0]), h0 = upk(a[1]);
        float2 l1 = upk(a[2]), h1 = upk(a[3]);
        int r0 = g0 + rg*2;
        float4 o0 = {fmaxf(l0.x+bb.x,0.f), fmaxf(l0.y+bb.y,0.f),
                     fmaxf(h0.x+bb.z,0.f), fmaxf(h0.y+bb.w,0.f)};
        float4 o1 = {fmaxf(l1.x+bb.x,0.f), fmaxf(l1.y+bb.y,0.f),
                     fmaxf(h1.x+bb.z,0.f), fmaxf(h1.y+bb.w,0.f)};
        *(float4*)(g_et + (r0+0)*D_ + wo) = o0;
        *(float4*)(g_et + (r0+1)*D_ + wo) = o1;
    }
}

// =====================================================================
// k_ih: 16 rows/block, grid 98. Wt[100x404] k-major, Xt[100x20]
// RT4 x CT8 -> 200 tasks
// =====================================================================
#define IH_WT 0
#define IH_X  40400
#define IH_XT 42000
#define IH_SM_FLOATS 44000
#define IH_SM_BYTES  (IH_SM_FLOATS*4)
__global__ __launch_bounds__(256, 1)
void k_ih(const float* __restrict__ Wih, const float* __restrict__ bih,
          const float* __restrict__ bhh)
{
    extern __shared__ float sm[];
    float* Wt = sm + IH_WT;
    float* X  = sm + IH_X;
    float* Xt = sm + IH_XT;
    int tid = threadIdx.x, g0 = blockIdx.x * 16;
    for (int i = tid; i < 40000; i += 256) {
        int o = i / 100, k = i % 100;
        Wt[k*404 + o] = Wih[i];
    }
    for (int i = tid; i < 1600; i += 256) X[i] = g_et[g0*D_ + i];
    __syncthreads();
    for (int i = tid; i < 1600; i += 256) {
        int k = i % 100, r = i / 100;
        Xt[k*20 + r] = X[r*100 + k];
    }
    __syncthreads();
    for (int task = tid; task < 200; task += 256) {
        int rg = task / 50, cq = task % 50, wo = cq*8;
        u64 a[16];
        #pragma unroll
        for (int i = 0; i < 16; i++) a[i] = 0;
        #pragma unroll 2
        for (int k = 0; k < 100; k++) {
            float4 xv = *(const float4*)(Xt + k*20 + rg*4);
            ulonglong2 wA = *(const ulonglong2*)(Wt + k*404 + wo);
            ulonglong2 wB = *(const ulonglong2*)(Wt + k*404 + wo + 4);
            u64 p0 = pk(xv.x), p1 = pk(xv.y), p2 = pk(xv.z), p3 = pk(xv.w);
            fmx(a[0],  p0, wA.x); fmx(a[1],  p0, wA.y); fmx(a[2],  p0, wB.x); fmx(a[3],  p0, wB.y);
            fmx(a[4],  p1, wA.x); fmx(a[5],  p1, wA.y); fmx(a[6],  p1, wB.x); fmx(a[7],  p1, wB.y);
            fmx(a[8],  p2, wA.x); fmx(a[9],  p2, wA.y); fmx(a[10], p2, wB.x); fmx(a[11], p2, wB.y);
            fmx(a[12], p3, wA.x); fmx(a[13], p3, wA.y); fmx(a[14], p3, wB.x); fmx(a[15], p3, wB.y);
        }
        float4 bi0 = *(const float4*)(bih + wo), bi1 = *(const float4*)(bih + wo + 4);
        float4 bh0 = *(const float4*)(bhh + wo), bh1 = *(const float4*)(bhh + wo + 4);
        float4 bbA = {bi0.x+bh0.x, bi0.y+bh0.y, bi0.z+bh0.z, bi0.w+bh0.w};
        float4 bbB = {bi1.x+bh1.x, bi1.y+bh1.y, bi1.z+bh1.z, bi1.w+bh1.w};
        #pragma unroll
        for (int r = 0; r < 4; r++) {
            int row = g0 + rg*4 + r;
            float2 p0 = upk(a[r*4+0]), p1 = upk(a[r*4+1]);
            float2 p2 = upk(a[r*4+2]), p3 = upk(a[r*4+3]);
            float4 oA = {p0.x+bbA.x, p0.y+bbA.y, p1.x+bbA.z, p1.y+bbA.w};
            float4 oB = {p2.x+bbB.x, p2.y+bbB.y, p3.x+bbB.z, p3.y+bbB.w};
            *(float4*)(g_preg + row*400 + wo)     = oA;
            *(float4*)(g_preg + row*400 + wo + 4) = oB;
        }
    }
}

// =====================================================================
// k_seq2: per-batch LSTM recurrence + in-block attention epilogue
// =====================================================================
__global__ __launch_bounds__(800, 1)
void k_seq2(const int* __restrict__ mask, const float* __restrict__ Whh,
            float* __restrict__ out)
{
    __shared__ float sh[TS_*D_];
    __shared__ float pp[800];
    __shared__ float h[104];
    __shared__ float vkS[104];
    __shared__ int maskS[T_];

    int b = blockIdx.x, tid = threadIdx.x;
    int lane = tid & 31, wid_ = tid >> 5;
    int o = tid >> 1, half = tid & 1;

    // W_hh half-row in registers, as 26 f32x2 pairs over consecutive k
    u64 w[26];
    {
        const float4* Wr = (const float4*)(Whh + o*D_ + half*52);
        #pragma unroll
        for (int j = 0; j < 13; j++) {
            if (half == 0 || j < 12) {
                float4 v = __ldg(Wr + j);
                asm("mov.b64 %0, {%1,%2};" : "=l"(w[2*j])   : "f"(v.x), "f"(v.y));
                asm("mov.b64 %0, {%1,%2};" : "=l"(w[2*j+1]) : "f"(v.z), "f"(v.w));
            } else { w[2*j] = 0; w[2*j+1] = 0; }
        }
    }
    float creg = 0.f;
    if (tid < 104) { h[tid] = 0.f; vkS[tid] = (tid < D_) ? g_vk[tid] : 0.f; }
    if (tid < T_) maskS[tid] = mask[b*T_ + tid];
    if (tid == 0) out[b*T_] = 0.5f;
    __syncthreads();

    for (int t = 0; t < TS_; t++) {
        const float* G0 = g_preg + (size_t)(b*TS_ + t) * 400;
        float gI=0.f, gF=0.f, gG=0.f, gO=0.f;
        if (tid < D_) {
            gI = __ldg(G0 + tid);        gF = __ldg(G0 + D_ + tid);
            gG = __ldg(G0 + 2*D_ + tid); gO = __ldg(G0 + 3*D_ + tid);
        }
        // partial GEMV with f32x2
        {
            u64 acc = 0;
            const ulonglong2* h2 = (const ulonglong2*)(h + half*52);
            int nj = (half == 0) ? 13 : 12;
            #pragma unroll 13
            for (int j = 0; j < 13; j++) {
                if (j < nj) {
                    ulonglong2 hv = h2[j];
                    fmx(acc, hv.x, w[2*j]);
                    fmx(acc, hv.y, w[2*j+1]);
                }
            }
            float2 f = upk(acc);
            pp[tid] = f.x + f.y;
        }
        __syncthreads();
        if (tid < D_) {
            int d2 = tid*2;
            float ai = gI + pp[d2]       + pp[d2+1];
            float af = gF + pp[200 + d2] + pp[200 + d2+1];
            float ag = gG + pp[400 + d2] + pp[400 + d2+1];
            float ao = gO + pp[600 + d2] + pp[600 + d2+1];
            float c2 = fast_sig(af) * creg + fast_sig(ai) * fast_tanh(ag);
            float h2v = fast_sig(ao) * fast_tanh(c2);
            if (maskS[t]) { creg = c2; h[tid] = h2v; }
            sh[t*D_ + tid] = h[tid];
        }
        __syncthreads();
    }

    // ---- attention epilogue: t parallel across 25 warps ----
    for (int t = wid_; t < TS_; t += 25) {
        int row = b*TS_ + t;
        const float* up = g_u + (size_t)row*D_;
        float u0 = up[lane], u1 = up[32+lane], u2 = up[64+lane];
        float u3 = (lane < 4) ? up[96+lane] : 0.f;
        float kl[11], dt[11];
        #pragma unroll
        for (int j = 0; j < 11; j++) {
            int rr = (j == 0) ? t : g_topk[row*10 + j - 1];
            float s1 = 0.f, s2 = 0.f;
            if (rr >= 0) {
                const float* hp = sh + rr*D_;
                float h0 = hp[lane], h1 = hp[32+lane], h2v = hp[64+lane];
                float h3 = (lane < 4) ? hp[96+lane] : 0.f;
                s1 = h0*vkS[lane] + h1*vkS[32+lane] + h2v*vkS[64+lane]
                   + ((lane < 4) ? h3*vkS[96+lane] : 0.f);
                s2 = h0*u0 + h1*u1 + h2v*u2 + h3*u3;
            }
            for (int off = 16; off; off >>= 1) {
                s1 += __shfl_down_sync(0xffffffffu, s1, off);
                s2 += __shfl_down_sync(0xffffffffu, s2, off);
            }
            kl[j] = (rr >= 0) ? s1 : NEGF;
            dt[j] = (rr >= 0) ? s2 : 0.f;
        }
        if (lane == 0) {
            float mx = kl[0];
            #pragma unroll
            for (int j = 1; j < 11; j++) mx = fmaxf(mx, kl[j]);
            float z = 0.f, num = 0.f;
            #pragma unroll
            for (int j = 0; j < 11; j++) {
                float e = __expf(kl[j] - mx);
                z += e; num += e * dt[j];
            }
            float y = num / (g_zq[row] * z);
            out[b*T_ + t + 1] = fast_sig(y);
        }
    }
}

// =====================================================================
// launch
// =====================================================================
extern "C" void kernel_launch(void* const* d_in, const int* in_sizes, int n_in,
                              void* d_out, int out_size)
{
    const int*   user      = (const int*)  d_in[0];
    const int*   question  = (const int*)  d_in[1];
    const int*   response  = (const int*)  d_in[2];
    const int*   mask      = (const int*)  d_in[3];
    const int*   q_nb      = (const int*)  d_in[4];
    const int*   s_nb      = (const int*)  d_in[5];
    const int*   u_nb      = (const int*)  d_in[6];
    const int*   q_nb2     = (const int*)  d_in[7];
    const int*   qsi       = (const int*)  d_in[8];
    const float* emb_q     = (const float*)d_in[9];
    const float* emb_q2    = (const float*)d_in[10];
    const float* emb_s     = (const float*)d_in[11];
    const float* emb_u     = (const float*)d_in[12];
    const float* emb_r     = (const float*)d_in[13];
    const float* w1p       = (const float*)d_in[14];
    const float* w2p       = (const float*)d_in[15];
    const float* W_ih      = (const float*)d_in[16];
    const float* W_hh      = (const float*)d_in[17];
    const float* b_ih      = (const float*)d_in[18];
    const float* b_hh      = (const float*)d_in[19];
    const float* agg_w     = (const float*)d_in[20];
    const float* agg_b     = (const float*)d_in[21];
    const float* W_al      = (const float*)d_in[22];
    const float* b_al      = (const float*)d_in[23];
    const float* W_q       = (const float*)d_in[24];
    const float* W_k       = (const float*)d_in[26];
    const float* W_w       = (const float*)d_in[28];
    const float* W_f       = (const float*)d_in[30];
    const float* b_f       = (const float*)d_in[31];
    float* out = (float*)d_out;
    (void)in_sizes; (void)n_in; (void)out_size;

    cudaFuncSetAttribute(k_agg,  cudaFuncAttributeMaxDynamicSharedMemorySize, AGG_SM_BYTES);
    cudaFuncSetAttribute(k_fuse, cudaFuncAttributeMaxDynamicSharedMemorySize, FUSE_SM_BYTES);
    cudaFuncSetAttribute(k_ih,   cudaFuncAttributeMaxDynamicSharedMemorySize, IH_SM_BYTES);

    k_prep<<<1, 128>>>(W_q, W_k, W_w);
    k_agg<<<148, 512, AGG_SM_BYTES>>>(question, user, mask,
        q_nb, s_nb, u_nb, q_nb2, emb_q, emb_q2, emb_s, emb_u,
        agg_w, agg_b, W_al, b_al);
    k_att<<<dim3(TS_, B_), 256>>>(question, qsi, emb_q, emb_s);
    k_fuse<<<98, 256, FUSE_SM_BYTES>>>(response, emb_r, w1p, w2p, W_f, b_f);
    k_ih<<<98, 256, IH_SM_BYTES>>>(W_ih, b_ih, b_hh);
    k_seq2<<<B_, 800>>>(mask, W_hh, out);
}